// round 4
// baseline (speedup 1.0000x reference)
#include <cuda_runtime.h>
#include <stdint.h>

#define NN 2048
#define NW 64   // 2048 bits = 64 u32 words

// ---------------- device scratch ----------------
__device__ uint32_t g_apT[NN*NW];        // A_pos^T bits
__device__ uint32_t g_lastT0[NN*NW];
__device__ uint32_t g_lastT1[NN*NW];
__device__ uint32_t g_U[6*NN*NW];        // union bits per stage (row-major)
__device__ int      g_pc[6*NN];          // popcount per stage
__device__ float    g_dinv[6*NN];        // rsqrt(pc+1) per stage
__device__ float    g_cs[6*256];         // colsum of dinv.*h per stage
__device__ float    g_h1[NN*256];
__device__ float    g_x1[NN*256];
__device__ float    g_bufA[NN*64];
__device__ float    g_bufB[NN*64];

// ---------------- zero pc + cs ----------------
__global__ void zero_kernel(int* __restrict__ pc, float* __restrict__ cs)
{
    int i = blockIdx.x*blockDim.x + threadIdx.x;
    if (i < 6*NN)  pc[i] = 0;
    if (i < 6*256) cs[i] = 0.f;
}

// ---------------- pack A_pos -> transposed bits ----------------
__global__ void packT_pos_kernel(const float* __restrict__ A, uint32_t* __restrict__ apT)
{
    int gwarp = (blockIdx.x*blockDim.x + threadIdx.x) >> 5;
    int lane  = threadIdx.x & 31;
    int ti = gwarp >> 6;   // row tile
    int tj = gwarp & 63;   // col tile
    uint32_t tbits = 0;
#pragma unroll
    for (int r = 0; r < 32; r++) {
        float v = A[(size_t)(ti*32 + r)*NN + tj*32 + lane];
        tbits |= (v > 0.f ? 1u : 0u) << r;
    }
    apT[(tj*32 + lane)*NW + ti] = tbits;
}

// ---------------- pack A_neg -> U0 (row bits) + lastT0 + pc0 ----------------
__global__ void pack_neg_kernel(const float* __restrict__ A, uint32_t* __restrict__ u0,
                                uint32_t* __restrict__ lastT, int* __restrict__ pc0)
{
    int gwarp = (blockIdx.x*blockDim.x + threadIdx.x) >> 5;
    int lane  = threadIdx.x & 31;
    int ti = gwarp >> 6;
    int tj = gwarp & 63;
    uint32_t tbits = 0, rw = 0;
#pragma unroll
    for (int r = 0; r < 32; r++) {
        float v = A[(size_t)(ti*32 + r)*NN + tj*32 + lane];
        uint32_t b = (v > 0.f) ? 1u : 0u;
        tbits |= b << r;
        uint32_t m = __ballot_sync(0xffffffffu, b);
        if (lane == r) rw = m;
    }
    u0[(ti*32 + lane)*NW + tj] = rw;
    atomicAdd(&pc0[ti*32 + lane], __popc(rw));
    lastT[(tj*32 + lane)*NW + ti] = tbits;
}

// ---------------- dinv from pc ----------------
__global__ void dinv_kernel(const int* __restrict__ pc, float* __restrict__ dinv)
{
    int i = blockIdx.x*blockDim.x + threadIdx.x;
    if (i < NN) dinv[i] = rsqrtf((float)(pc[i] + 1));
}

// ---------------- expansion in transposed domain ----------------
__global__ void expandT_kernel(const uint32_t* __restrict__ lastOld, uint32_t* __restrict__ lastNew,
                               const uint32_t* __restrict__ apT)
{
    __shared__ uint32_t sh[4][64];
    int w = threadIdx.x;
    int y = threadIdx.y;
    int j = blockIdx.x*4 + y;
    sh[y][w] = apT[j*NW + w];
    __syncthreads();
    uint32_t acc = 0;
    for (int w2 = 0; w2 < NW; w2++) {
        uint32_t m = sh[y][w2];
        while (m) {
            int b = __ffs(m) - 1; m &= (m-1);
            acc |= lastOld[(w2*32 + b)*NW + w];
        }
    }
    lastNew[j*NW + w] = acc;
}

// ---------------- transpose lastNew, OR with uPrev -> uCur, accumulate pc ----------------
__global__ void transpose_or_kernel(const uint32_t* __restrict__ lastNew,
                                    const uint32_t* __restrict__ uPrev,
                                    uint32_t* __restrict__ uCur, int* __restrict__ pcCur)
{
    __shared__ uint32_t sh[32][65];
    int tid = threadIdx.x;
    int ti = blockIdx.x;
    for (int idx = tid; idx < 32*64; idx += blockDim.x) {
        int r = idx >> 6, c = idx & 63;
        sh[r][c] = lastNew[(ti*32 + r)*NW + c];
    }
    __syncthreads();
    int warp = tid >> 5, lane = tid & 31;
    for (int tj = warp; tj < 64; tj += 8) {
        uint32_t v = sh[lane][tj];
        uint32_t ow = 0;
#pragma unroll
        for (int jb = 0; jb < 32; jb++) {
            uint32_t m = __ballot_sync(0xffffffffu, (v >> jb) & 1u);
            if (lane == jb) ow = m;
        }
        int j = tj*32 + lane;
        uint32_t merged = uPrev[j*NW + ti] | ow;
        uCur[j*NW + ti] = merged;
        atomicAdd(&pcCur[j], __popc(merged));
    }
}

// ---------------- SGEMM (64x64 tile, K-chunk 16) + bias + fused colsum ----------------
__global__ void gemm_kernel(const float* __restrict__ A, int lda, int K,
                            const float* __restrict__ W, int ldw, int Nc,
                            const float* __restrict__ bias,
                            float* __restrict__ C, int ldc,
                            const float* __restrict__ dinvS,
                            float* __restrict__ cs)
{
    __shared__ __align__(16) float As[16][68];
    __shared__ __align__(16) float Ws[16][64];
    __shared__ float red[16][64];
    int tid = threadIdx.x;
    int tx = tid & 15, ty = tid >> 4;
    int rowBase = blockIdx.y*64, colBase = blockIdx.x*64;
    float acc[4][4] = {};
    int mA = tid >> 2, kqA = (tid & 3)*4;
    int kkW = tid >> 4, cW = (tid & 15)*4;

    for (int k0 = 0; k0 < K; k0 += 16) {
#pragma unroll
        for (int l = 0; l < 4; l++) {
            int kk = kqA + l;
            As[kk][mA] = (k0+kk < K) ? A[(size_t)(rowBase+mA)*lda + k0 + kk] : 0.f;
        }
#pragma unroll
        for (int l = 0; l < 4; l++) {
            int c = cW + l;
            Ws[kkW][c] = (k0+kkW < K && colBase+c < Nc) ? W[(size_t)(k0+kkW)*ldw + colBase + c] : 0.f;
        }
        __syncthreads();
#pragma unroll
        for (int kk = 0; kk < 16; kk++) {
            float4 av = *(const float4*)&As[kk][ty*4];
            float4 bv = *(const float4*)&Ws[kk][tx*4];
            float a4[4] = {av.x, av.y, av.z, av.w};
            float b4[4] = {bv.x, bv.y, bv.z, bv.w};
#pragma unroll
            for (int a = 0; a < 4; a++)
#pragma unroll
                for (int b = 0; b < 4; b++)
                    acc[a][b] += a4[a] * b4[b];
        }
        __syncthreads();
    }

    float p[4] = {0.f, 0.f, 0.f, 0.f};
#pragma unroll
    for (int a = 0; a < 4; a++) {
        int row = rowBase + ty*4 + a;
        float di = dinvS[row];
#pragma unroll
        for (int b = 0; b < 4; b++) {
            int col = colBase + tx*4 + b;
            float val = acc[a][b] + ((col < Nc) ? bias[col] : 0.f);
            C[(size_t)row*ldc + col] = val;
            p[b] += di * val;
        }
    }
#pragma unroll
    for (int b = 0; b < 4; b++) red[ty][tx*4 + b] = p[b];
    __syncthreads();
    if (tid < 64) {
        float s = 0.f;
#pragma unroll
        for (int t = 0; t < 16; t++) s += red[t][tid];
        atomicAdd(&cs[colBase + tid], s);
    }
}

// ---------------- stage 1 fused agg + z@W_g1 + epilogue (F=256) ----------------
__global__ void agg1_kernel(const float* __restrict__ h,      // h1 2048x256
                            const float* __restrict__ Wg,     // 256x256
                            const float* __restrict__ bias,
                            const float* __restrict__ dinvS,
                            const int* __restrict__ pcS,
                            const uint32_t* __restrict__ u,
                            const float* __restrict__ cs,
                            float* __restrict__ outp)         // x1 2048x256
{
    __shared__ float sDinv[NN];
    __shared__ uint32_t sU[8][64];
    __shared__ float sZ[8][256];
    int tid = threadIdx.x;     // 512
    int row0 = blockIdx.x*8;

    for (int t = tid; t < NN; t += 512) sDinv[t] = dinvS[t];
    { int r = tid >> 6, c = tid & 63; sU[r][c] = u[(row0 + r)*NW + c]; }
    __syncthreads();

    // phase 1: z = dinv_i*(S + dinv_i*h_i)
    {
        int lane = tid & 63, grp = tid >> 6;
        int row = row0 + grp;
        int f = lane*4;
        bool comp = pcS[row] > 1024;
        float4 acc = make_float4(0.f,0.f,0.f,0.f);
        for (int w2 = 0; w2 < NW; w2++) {
            uint32_t m = sU[grp][w2];
            if (comp) m = ~m;
            int kb = w2*32;
            while (m) {
                int b = __ffs(m) - 1; m &= (m-1);
                int k = kb + b;
                float4 v = *(const float4*)(h + (size_t)k*256 + f);
                float d = sDinv[k];
                acc.x += d*v.x; acc.y += d*v.y; acc.z += d*v.z; acc.w += d*v.w;
            }
        }
        if (comp) {
            float4 c4 = *(const float4*)(cs + f);
            acc.x = c4.x - acc.x; acc.y = c4.y - acc.y;
            acc.z = c4.z - acc.z; acc.w = c4.w - acc.w;
        }
        float di = sDinv[row];
        float4 hv = *(const float4*)(h + (size_t)row*256 + f);
        sZ[grp][f+0] = di*(acc.x + di*hv.x);
        sZ[grp][f+1] = di*(acc.y + di*hv.y);
        sZ[grp][f+2] = di*(acc.z + di*hv.z);
        sZ[grp][f+3] = di*(acc.w + di*hv.w);
    }
    __syncthreads();

    // phase 2: x1 = h1 + relu(z @ Wg + bias)
    {
        int r = tid >> 6;
        int c = (tid & 63)*4;
        int row = row0 + r;
        float a0=0.f, a1=0.f, a2=0.f, a3=0.f;
#pragma unroll 4
        for (int k = 0; k < 256; k++) {
            float zv = sZ[r][k];
            float4 wv = *(const float4*)(Wg + (size_t)k*256 + c);
            a0 += zv*wv.x; a1 += zv*wv.y; a2 += zv*wv.z; a3 += zv*wv.w;
        }
        float4 b4 = *(const float4*)(bias + c);
        float4 hv = *(const float4*)(h + (size_t)row*256 + c);
        float4 o;
        o.x = hv.x + fmaxf(a0 + b4.x, 0.f);
        o.y = hv.y + fmaxf(a1 + b4.y, 0.f);
        o.z = hv.z + fmaxf(a2 + b4.z, 0.f);
        o.w = hv.w + fmaxf(a3 + b4.w, 0.f);
        *(float4*)(outp + (size_t)row*256 + c) = o;
    }
}

// ---------------- stages 2-6 fused agg + z@W_g + epilogue (F<=64) ----------------
__global__ void agg64_kernel(const float* __restrict__ h,      // 2048x64 (padded)
                             const float* __restrict__ Wg, int ldw, int Nc,
                             const float* __restrict__ bias,
                             const float* __restrict__ dinvS,
                             const int* __restrict__ pcS,
                             const uint32_t* __restrict__ u,
                             const float* __restrict__ cs,
                             float* __restrict__ outp,
                             float wscale, int doRelu,
                             const float* __restrict__ dinvNext,
                             float* __restrict__ csNext)
{
    __shared__ float sDinv[NN];
    __shared__ uint32_t sU[16][64];
    __shared__ float sZ[16][64];
    __shared__ float sW[64][64];
    __shared__ float red[16][64];
    int tid = threadIdx.x;    // 256
    int row0 = blockIdx.x*16;

    for (int t = tid; t < NN; t += 256) sDinv[t] = dinvS[t];
    for (int t = tid; t < 16*64; t += 256) {
        int r = t >> 6, c = t & 63;
        sU[r][c] = u[(row0 + r)*NW + c];
    }
    for (int t = tid; t < 64*64; t += 256) {
        int k = t >> 6, c = t & 63;
        sW[k][c] = (k < Nc && c < Nc) ? Wg[(size_t)k*ldw + c] : 0.f;
    }
    __syncthreads();

    // phase 1: aggregation -> z
    {
        int lane = tid & 15, grp = tid >> 4;
        int row = row0 + grp;
        int f = lane*4;
        bool comp = pcS[row] > 1024;
        float4 acc = make_float4(0.f,0.f,0.f,0.f);
        for (int w2 = 0; w2 < NW; w2++) {
            uint32_t m = sU[grp][w2];
            if (comp) m = ~m;
            int kb = w2*32;
            while (m) {
                int b = __ffs(m) - 1; m &= (m-1);
                int k = kb + b;
                float4 v = *(const float4*)(h + (size_t)k*64 + f);
                float d = sDinv[k];
                acc.x += d*v.x; acc.y += d*v.y; acc.z += d*v.z; acc.w += d*v.w;
            }
        }
        if (comp) {
            float4 c4 = *(const float4*)(cs + f);
            acc.x = c4.x - acc.x; acc.y = c4.y - acc.y;
            acc.z = c4.z - acc.z; acc.w = c4.w - acc.w;
        }
        float di = sDinv[row];
        float4 hv = *(const float4*)(h + (size_t)row*64 + f);
        sZ[grp][f+0] = di*(acc.x + di*hv.x);
        sZ[grp][f+1] = di*(acc.y + di*hv.y);
        sZ[grp][f+2] = di*(acc.z + di*hv.z);
        sZ[grp][f+3] = di*(acc.w + di*hv.w);
    }
    __syncthreads();

    // phase 2: out = h + wscale*act(z @ Wg + bias); optional colsum for next stage
    {
        int r = tid >> 4;
        int c = (tid & 15)*4;
        int row = row0 + r;
        float a0=0.f, a1=0.f, a2=0.f, a3=0.f;
#pragma unroll 8
        for (int k = 0; k < 64; k++) {
            float zv = sZ[r][k];
            a0 += zv*sW[k][c+0];
            a1 += zv*sW[k][c+1];
            a2 += zv*sW[k][c+2];
            a3 += zv*sW[k][c+3];
        }
        float o[4] = {a0, a1, a2, a3};
        float dN = csNext ? dinvNext[row] : 0.f;
#pragma unroll
        for (int j = 0; j < 4; j++) {
            int cc = c + j;
            float b = (cc < Nc) ? bias[cc] : 0.f;
            float v = o[j] + b;
            if (doRelu) v = fmaxf(v, 0.f);
            float res = h[(size_t)row*64 + cc] + wscale*v;
            outp[(size_t)row*64 + cc] = res;
            red[r][cc] = dN*res;
        }
    }
    if (csNext) {
        __syncthreads();
        if (tid < 64) {
            float s = 0.f;
#pragma unroll
            for (int r = 0; r < 16; r++) s += red[r][tid];
            atomicAdd(&csNext[tid], s);
        }
    }
}

// ---------------- host ----------------
static void* sym(const void* s) { void* p = nullptr; cudaGetSymbolAddress(&p, s); return p; }

extern "C" void kernel_launch(void* const* d_in, const int* in_sizes, int n_in,
                              void* d_out, int out_size)
{
    const float* x    = (const float*)d_in[0];
    const float* Aneg = (const float*)d_in[1];
    const float* Apos = (const float*)d_in[2];
    const float* W_l1 = (const float*)d_in[3];  const float* b_l1 = (const float*)d_in[4];
    const float* W_l2 = (const float*)d_in[5];  const float* b_l2 = (const float*)d_in[6];
    const float* W_l3 = (const float*)d_in[7];  const float* b_l3 = (const float*)d_in[8];
    const float* W_g1 = (const float*)d_in[9];  const float* b_g1 = (const float*)d_in[10];
    const float* W_g2 = (const float*)d_in[11]; const float* b_g2 = (const float*)d_in[12];
    const float* W_g3 = (const float*)d_in[13]; const float* b_g3 = (const float*)d_in[14];
    const float* W_g4 = (const float*)d_in[15]; const float* b_g4 = (const float*)d_in[16];
    const float* W_g5 = (const float*)d_in[17]; const float* b_g5 = (const float*)d_in[18];
    const float* W_g6 = (const float*)d_in[19]; const float* b_g6 = (const float*)d_in[20];
    float* out = (float*)d_out;

    uint32_t* apT    = (uint32_t*)sym(g_apT);
    uint32_t* lastT0 = (uint32_t*)sym(g_lastT0);
    uint32_t* lastT1 = (uint32_t*)sym(g_lastT1);
    uint32_t* U      = (uint32_t*)sym(g_U);
    int*   pc   = (int*)sym(g_pc);
    float* dinv = (float*)sym(g_dinv);
    float* cs   = (float*)sym(g_cs);
    float* h1   = (float*)sym(g_h1);
    float* x1   = (float*)sym(g_x1);
    float* bufA = (float*)sym(g_bufA);
    float* bufB = (float*)sym(g_bufB);

    // persistent side stream + events (created once; identical captured work every call)
    static cudaStream_t sB = nullptr;
    static cudaEvent_t evF = nullptr;
    static cudaEvent_t ev[6];
    if (!sB) {
        cudaStreamCreateWithFlags(&sB, cudaStreamNonBlocking);
        cudaEventCreateWithFlags(&evF, cudaEventDisableTiming);
        for (int i = 0; i < 6; i++) cudaEventCreateWithFlags(&ev[i], cudaEventDisableTiming);
    }

    dim3 exp_blk(64, 4);

    // ---- fork: bit chain on side stream ----
    cudaEventRecord(evF, 0);
    cudaStreamWaitEvent(sB, evF, 0);

    zero_kernel<<<48, 256, 0, sB>>>(pc, cs);
    packT_pos_kernel<<<512, 256, 0, sB>>>(Apos, apT);
    pack_neg_kernel<<<512, 256, 0, sB>>>(Aneg, U, lastT0, pc);
    dinv_kernel<<<8, 256, 0, sB>>>(pc, dinv);
    cudaEventRecord(ev[0], sB);

    uint32_t* lt[2] = {lastT0, lastT1};
    for (int s = 1; s <= 5; s++) {
        expandT_kernel<<<512, exp_blk, 0, sB>>>(lt[(s+1)&1], lt[s&1], apT);
        transpose_or_kernel<<<64, 256, 0, sB>>>(lt[s&1], U + (size_t)(s-1)*NN*NW,
                                                U + (size_t)s*NN*NW, pc + s*NN);
        dinv_kernel<<<8, 256, 0, sB>>>(pc + s*NN, dinv + s*NN);
        cudaEventRecord(ev[s], sB);
    }

    // ---- float chain on main stream ----
    cudaStreamWaitEvent(0, ev[0], 0);
    // stage 1
    gemm_kernel<<<dim3(4,32), 256>>>(x, 512, 512, W_l1, 256, 256, b_l1, h1, 256, dinv, cs);
    agg1_kernel<<<256, 512>>>(h1, W_g1, b_g1, dinv, pc, U, cs, x1);

    // stage 2 (Nc=62)
    cudaStreamWaitEvent(0, ev[1], 0);
    gemm_kernel<<<dim3(1,32), 256>>>(x1, 256, 256, W_l2, 62, 62, b_l2, bufA, 64,
                                     dinv + NN, cs + 256);
    agg64_kernel<<<128, 256>>>(bufA, W_g2, 62, 62, b_g2,
                               dinv + NN, pc + NN, U + (size_t)NN*NW, cs + 256,
                               bufB, 1.0f, 1, nullptr, nullptr);

    // stage 3 (Nc=64, w=0.5) ; epilogue produces cs for stage 4
    cudaStreamWaitEvent(0, ev[2], 0);
    gemm_kernel<<<dim3(1,32), 256>>>(bufB, 64, 62, W_l3, 64, 64, b_l3, bufA, 64,
                                     dinv + 2*NN, cs + 2*256);
    cudaStreamWaitEvent(0, ev[3], 0);
    agg64_kernel<<<128, 256>>>(bufA, W_g3, 64, 64, b_g3,
                               dinv + 2*NN, pc + 2*NN, U + (size_t)2*NN*NW, cs + 2*256,
                               bufB, 0.5f, 1, dinv + 3*NN, cs + 3*256);

    // stage 4 (h = x3, w=0.5) ; produces cs for stage 5
    cudaStreamWaitEvent(0, ev[4], 0);
    agg64_kernel<<<128, 256>>>(bufB, W_g4, 64, 64, b_g4,
                               dinv + 3*NN, pc + 3*NN, U + (size_t)3*NN*NW, cs + 3*256,
                               bufA, 0.5f, 1, dinv + 4*NN, cs + 4*256);

    // stage 5 (w=0.25) ; produces cs for stage 6
    cudaStreamWaitEvent(0, ev[5], 0);
    agg64_kernel<<<128, 256>>>(bufA, W_g5, 64, 64, b_g5,
                               dinv + 4*NN, pc + 4*NN, U + (size_t)4*NN*NW, cs + 4*256,
                               bufB, 0.25f, 1, dinv + 5*NN, cs + 5*256);

    // stage 6 (w=0.25, no relu) -> d_out
    agg64_kernel<<<128, 256>>>(bufB, W_g6, 64, 64, b_g6,
                               dinv + 5*NN, pc + 5*NN, U + (size_t)5*NN*NW, cs + 5*256,
                               out, 0.25f, 0, nullptr, nullptr);
}

// round 5
// speedup vs baseline: 1.0370x; 1.0370x over previous
#include <cuda_runtime.h>
#include <stdint.h>

#define NN 2048
#define NW 64   // 2048 bits = 64 u32 words

// ---------------- device scratch ----------------
__device__ uint32_t g_apT[NN*NW];        // A_pos^T bits
__device__ uint32_t g_lastT0[NN*NW];
__device__ uint32_t g_lastT1[NN*NW];
__device__ uint32_t g_U[6*NN*NW];        // union bits per stage (row-major)
__device__ int      g_pc[6*NN];          // popcount per stage
__device__ float    g_cs[6*256];         // colsum of dinv.*h per stage
__device__ float    g_h1[NN*256];
__device__ float    g_bufA[NN*64];
__device__ float    g_bufB[NN*64];

// ---------------- zero pc + cs ----------------
__global__ void zero_kernel(int* __restrict__ pc, float* __restrict__ cs)
{
    int i = blockIdx.x*blockDim.x + threadIdx.x;
    if (i < 6*NN)  pc[i] = 0;
    if (i < 6*256) cs[i] = 0.f;
}

// ---------------- merged pack: blocks [0,512): A_pos->apT ; [512,1024): A_neg->U0,lastT0,pc0 ----------------
__global__ void pack_kernel(const float* __restrict__ Apos, const float* __restrict__ Aneg,
                            uint32_t* __restrict__ apT,
                            uint32_t* __restrict__ u0, uint32_t* __restrict__ lastT,
                            int* __restrict__ pc0)
{
    int lane = threadIdx.x & 31;
    if (blockIdx.x < 512) {
        int gwarp = blockIdx.x*8 + (threadIdx.x >> 5);
        int ti = gwarp >> 6, tj = gwarp & 63;
        uint32_t tbits = 0;
#pragma unroll
        for (int r = 0; r < 32; r++) {
            float v = Apos[(size_t)(ti*32 + r)*NN + tj*32 + lane];
            tbits |= (v > 0.f ? 1u : 0u) << r;
        }
        apT[(tj*32 + lane)*NW + ti] = tbits;
    } else {
        int gwarp = (blockIdx.x - 512)*8 + (threadIdx.x >> 5);
        int ti = gwarp >> 6, tj = gwarp & 63;
        uint32_t tbits = 0, rw = 0;
#pragma unroll
        for (int r = 0; r < 32; r++) {
            float v = Aneg[(size_t)(ti*32 + r)*NN + tj*32 + lane];
            uint32_t b = (v > 0.f) ? 1u : 0u;
            tbits |= b << r;
            uint32_t m = __ballot_sync(0xffffffffu, b);
            if (lane == r) rw = m;
        }
        u0[(ti*32 + lane)*NW + tj] = rw;
        atomicAdd(&pc0[ti*32 + lane], __popc(rw));
        lastT[(tj*32 + lane)*NW + ti] = tbits;
    }
}

// ---------------- fused bit stage: expand (transposed domain) + transpose + OR + pc ----------------
// Block b owns lastT rows j = b*32..b*32+31 (i.e. original columns), emits word b of every union row.
__global__ void __launch_bounds__(256) bitstage_kernel(
        const uint32_t* __restrict__ lastOld, uint32_t* __restrict__ lastNew,
        const uint32_t* __restrict__ apT,
        const uint32_t* __restrict__ uPrev, uint32_t* __restrict__ uCur,
        int* __restrict__ pcCur)
{
    __shared__ uint32_t sA[32][64];   // apT rows (neighbor masks of columns j)
    __shared__ uint32_t sN[32][65];   // expanded lastNew tile
    int b = blockIdx.x, tid = threadIdx.x;
    for (int t = tid; t < 32*64; t += 256)
        sA[t>>6][t&63] = apT[(b*32 + (t>>6))*NW + (t&63)];
    __syncthreads();

    int w = tid & 63, y = tid >> 6;   // 4 j's per round, 8 rounds
#pragma unroll 1
    for (int rnd = 0; rnd < 8; rnd++) {
        int jj = rnd*4 + y;
        uint32_t acc = 0;
        for (int w2 = 0; w2 < NW; w2++) {
            uint32_t m = sA[jj][w2];
            while (m) {
                int bb = __ffs(m) - 1; m &= (m-1);
                acc |= lastOld[(w2*32 + bb)*NW + w];
            }
        }
        sN[jj][w] = acc;
        lastNew[(b*32 + jj)*NW + w] = acc;
    }
    __syncthreads();

    int warp = tid >> 5, lane = tid & 31;
    for (int wq = warp; wq < 64; wq += 8) {
        uint32_t v = sN[lane][wq];
        uint32_t ow = 0;
#pragma unroll
        for (int ib = 0; ib < 32; ib++) {
            uint32_t mm = __ballot_sync(0xffffffffu, (v >> ib) & 1u);
            if (lane == ib) ow = mm;
        }
        int i = wq*32 + lane;
        uint32_t merged = uPrev[i*NW + b] | ow;
        uCur[i*NW + b] = merged;
        atomicAdd(&pcCur[i], __popc(merged));
    }
}

// ---------------- SGEMM (64x64 tile, Kc16) + bias + fused colsum ----------------
__global__ void gemm_kernel(const float* __restrict__ A, int lda, int K,
                            const float* __restrict__ W, int ldw, int Nc,
                            const float* __restrict__ bias,
                            float* __restrict__ C, int ldc,
                            const int* __restrict__ pcS,
                            float* __restrict__ cs)
{
    __shared__ __align__(16) float As[16][68];
    __shared__ __align__(16) float Ws[16][64];
    __shared__ float red[16][64];
    int tid = threadIdx.x;
    int tx = tid & 15, ty = tid >> 4;
    int rowBase = blockIdx.y*64, colBase = blockIdx.x*64;
    float acc[4][4] = {};
    int mA = tid >> 2, kqA = (tid & 3)*4;
    int kkW = tid >> 4, cW = (tid & 15)*4;

    for (int k0 = 0; k0 < K; k0 += 16) {
#pragma unroll
        for (int l = 0; l < 4; l++) {
            int kk = kqA + l;
            As[kk][mA] = (k0+kk < K) ? A[(size_t)(rowBase+mA)*lda + k0 + kk] : 0.f;
        }
#pragma unroll
        for (int l = 0; l < 4; l++) {
            int c = cW + l;
            Ws[kkW][c] = (k0+kkW < K && colBase+c < Nc) ? W[(size_t)(k0+kkW)*ldw + colBase + c] : 0.f;
        }
        __syncthreads();
#pragma unroll
        for (int kk = 0; kk < 16; kk++) {
            float4 av = *(const float4*)&As[kk][ty*4];
            float4 bv = *(const float4*)&Ws[kk][tx*4];
            float a4[4] = {av.x, av.y, av.z, av.w};
            float b4[4] = {bv.x, bv.y, bv.z, bv.w};
#pragma unroll
            for (int a = 0; a < 4; a++)
#pragma unroll
                for (int bq = 0; bq < 4; bq++)
                    acc[a][bq] += a4[a] * b4[bq];
        }
        __syncthreads();
    }

    float p[4] = {0.f, 0.f, 0.f, 0.f};
#pragma unroll
    for (int a = 0; a < 4; a++) {
        int row = rowBase + ty*4 + a;
        float di = rsqrtf((float)(pcS[row] + 1));
#pragma unroll
        for (int bq = 0; bq < 4; bq++) {
            int col = colBase + tx*4 + bq;
            float val = acc[a][bq] + ((col < Nc) ? bias[col] : 0.f);
            C[(size_t)row*ldc + col] = val;
            p[bq] += di * val;
        }
    }
#pragma unroll
    for (int bq = 0; bq < 4; bq++) red[ty][tx*4 + bq] = p[bq];
    __syncthreads();
    if (tid < 64) {
        float s = 0.f;
#pragma unroll
        for (int t = 0; t < 16; t++) s += red[t][tid];
        atomicAdd(&cs[colBase + tid], s);
    }
}

// ---------------- stage 1: agg(F=256) + z@Wg1 + relu-residual + FUSED x1@W_l2 -> h2, cs1 ----------------
__global__ void __launch_bounds__(512) agg1_kernel(
        const float* __restrict__ h,      // h1 2048x256
        const float* __restrict__ Wg,     // W_g1 256x256
        const float* __restrict__ bg,
        const int* __restrict__ pcS,      // pc0
        const uint32_t* __restrict__ u,   // union0
        const float* __restrict__ cs,     // cs0
        const float* __restrict__ Wl,     // W_l2 256x62
        const float* __restrict__ bl,     // b_l2
        const int* __restrict__ pcNext,   // pc1
        float* __restrict__ csNext,       // cs1
        float* __restrict__ outp)         // h2 2048x64 (cols 62,63 = 0)
{
    __shared__ float sDinv[NN];
    __shared__ uint32_t sU[8][64];
    __shared__ float sZ[8][256];
    __shared__ float sX[8][256];
    __shared__ float sRed[8][64];
    int tid = threadIdx.x;
    int row0 = blockIdx.x*8;

    for (int t = tid; t < NN; t += 512) sDinv[t] = rsqrtf((float)(pcS[t] + 1));
    { int r = tid >> 6, c = tid & 63; sU[r][c] = u[(row0 + r)*NW + c]; }
    __syncthreads();

    // P1: z = dinv_i*(S + dinv_i*h_i)
    {
        int lane = tid & 63, grp = tid >> 6;
        int row = row0 + grp;
        int f = lane*4;
        bool comp = pcS[row] > 1024;
        float4 acc = make_float4(0.f,0.f,0.f,0.f);
        for (int w2 = 0; w2 < NW; w2++) {
            uint32_t m = sU[grp][w2];
            if (comp) m = ~m;
            int kb = w2*32;
            while (m) {
                int bq = __ffs(m) - 1; m &= (m-1);
                int k = kb + bq;
                float4 v = *(const float4*)(h + (size_t)k*256 + f);
                float d = sDinv[k];
                acc.x += d*v.x; acc.y += d*v.y; acc.z += d*v.z; acc.w += d*v.w;
            }
        }
        if (comp) {
            float4 c4 = *(const float4*)(cs + f);
            acc.x = c4.x - acc.x; acc.y = c4.y - acc.y;
            acc.z = c4.z - acc.z; acc.w = c4.w - acc.w;
        }
        float di = sDinv[row];
        float4 hv = *(const float4*)(h + (size_t)row*256 + f);
        sZ[grp][f+0] = di*(acc.x + di*hv.x);
        sZ[grp][f+1] = di*(acc.y + di*hv.y);
        sZ[grp][f+2] = di*(acc.z + di*hv.z);
        sZ[grp][f+3] = di*(acc.w + di*hv.w);
    }
    __syncthreads();

    // P2: x1 = h1 + relu(z @ Wg + bg) -> sX
    {
        int r = tid >> 6;
        int c = (tid & 63)*4;
        int row = row0 + r;
        float a0=0.f, a1=0.f, a2=0.f, a3=0.f;
#pragma unroll 4
        for (int k = 0; k < 256; k++) {
            float zv = sZ[r][k];
            float4 wv = *(const float4*)(Wg + (size_t)k*256 + c);
            a0 += zv*wv.x; a1 += zv*wv.y; a2 += zv*wv.z; a3 += zv*wv.w;
        }
        float4 b4 = *(const float4*)(bg + c);
        float4 hv = *(const float4*)(h + (size_t)row*256 + c);
        sX[r][c+0] = hv.x + fmaxf(a0 + b4.x, 0.f);
        sX[r][c+1] = hv.y + fmaxf(a1 + b4.y, 0.f);
        sX[r][c+2] = hv.z + fmaxf(a2 + b4.z, 0.f);
        sX[r][c+3] = hv.w + fmaxf(a3 + b4.w, 0.f);
    }
    __syncthreads();

    // P3: h2 = x1 @ W_l2 + b_l2 (62 cols, pad to 64); csNext += dinvNext*h2
    {
        int r = tid >> 6;
        int cc = tid & 63;
        int row = row0 + r;
        float val = 0.f;
        if (cc < 62) {
            float a = 0.f;
#pragma unroll 4
            for (int k = 0; k < 256; k++)
                a += sX[r][k] * Wl[(size_t)k*62 + cc];
            val = a + bl[cc];
        }
        outp[(size_t)row*64 + cc] = val;
        float dN = rsqrtf((float)(pcNext[row] + 1));
        sRed[r][cc] = dN*val;
    }
    __syncthreads();
    if (tid < 64) {
        float s = 0.f;
#pragma unroll
        for (int r = 0; r < 8; r++) s += sRed[r][tid];
        atomicAdd(&csNext[tid], s);
    }
}

// ---------------- stages 2-6: agg(F<=64) + z@Wg + residual [+ fused @Wl] + optional csNext ----------------
__global__ void __launch_bounds__(256) agg64_kernel(
        const float* __restrict__ h, int NcIn,
        const float* __restrict__ Wg, int ldwg,
        const float* __restrict__ bg,
        const int* __restrict__ pcS,
        const uint32_t* __restrict__ u,
        const float* __restrict__ cs,
        float wscale, int doRelu,
        const float* __restrict__ Wl,     // optional: NcIn x 64 (ld 64)
        const float* __restrict__ bl,
        const int* __restrict__ pcNext,   // optional (with csNext)
        float* __restrict__ csNext,
        float* __restrict__ outp)
{
    __shared__ float sDinv[NN];
    __shared__ uint32_t sU[16][64];
    __shared__ float sW[64][64];
    __shared__ float sZ[16][64];
    __shared__ float red[16][64];
    int tid = threadIdx.x;
    int row0 = blockIdx.x*16;

    for (int t = tid; t < NN; t += 256) sDinv[t] = rsqrtf((float)(pcS[t] + 1));
    for (int t = tid; t < 16*64; t += 256) {
        int r = t >> 6, c = t & 63;
        sU[r][c] = u[(row0 + r)*NW + c];
    }
    for (int t = tid; t < 64*64; t += 256) {
        int k = t >> 6, c = t & 63;
        sW[k][c] = (k < NcIn && c < NcIn) ? Wg[(size_t)k*ldwg + c] : 0.f;
    }
    __syncthreads();

    // P1: aggregation -> sZ (padded cols are exact zeros since h padded)
    {
        int lane = tid & 15, grp = tid >> 4;
        int row = row0 + grp;
        int f = lane*4;
        bool comp = pcS[row] > 1024;
        float4 acc = make_float4(0.f,0.f,0.f,0.f);
        for (int w2 = 0; w2 < NW; w2++) {
            uint32_t m = sU[grp][w2];
            if (comp) m = ~m;
            int kb = w2*32;
            while (m) {
                int bq = __ffs(m) - 1; m &= (m-1);
                int k = kb + bq;
                float4 v = *(const float4*)(h + (size_t)k*64 + f);
                float d = sDinv[k];
                acc.x += d*v.x; acc.y += d*v.y; acc.z += d*v.z; acc.w += d*v.w;
            }
        }
        if (comp) {
            float4 c4 = *(const float4*)(cs + f);
            acc.x = c4.x - acc.x; acc.y = c4.y - acc.y;
            acc.z = c4.z - acc.z; acc.w = c4.w - acc.w;
        }
        float di = sDinv[row];
        float4 hv = *(const float4*)(h + (size_t)row*64 + f);
        sZ[grp][f+0] = di*(acc.x + di*hv.x);
        sZ[grp][f+1] = di*(acc.y + di*hv.y);
        sZ[grp][f+2] = di*(acc.z + di*hv.z);
        sZ[grp][f+3] = di*(acc.w + di*hv.w);
    }
    __syncthreads();

    // P2: y = h + wscale*act(z@Wg + bg)
    int r = tid >> 4;
    int c = (tid & 15)*4;
    int row = row0 + r;
    float y[4] = {0.f, 0.f, 0.f, 0.f};
#pragma unroll 8
    for (int k = 0; k < 64; k++) {
        float zv = sZ[r][k];
        y[0] += zv*sW[k][c+0];
        y[1] += zv*sW[k][c+1];
        y[2] += zv*sW[k][c+2];
        y[3] += zv*sW[k][c+3];
    }
#pragma unroll
    for (int j = 0; j < 4; j++) {
        int cc = c + j;
        float b = (cc < NcIn) ? bg[cc] : 0.f;
        float v = y[j] + b;
        if (doRelu) v = fmaxf(v, 0.f);
        y[j] = h[(size_t)row*64 + cc] + wscale*v;
    }

    float val[4];
    if (Wl) {
        __syncthreads();                       // done reading sZ & sW
#pragma unroll
        for (int j = 0; j < 4; j++) sZ[r][c+j] = y[j];   // sZ <- y
        for (int t = tid; t < 64*64; t += 256) {
            int k = t >> 6, cc2 = t & 63;
            sW[k][cc2] = (k < NcIn) ? Wl[(size_t)k*64 + cc2] : 0.f;
        }
        __syncthreads();
        // P3: out = y @ Wl + bl
#pragma unroll
        for (int j = 0; j < 4; j++) val[j] = 0.f;
#pragma unroll 8
        for (int k = 0; k < 64; k++) {
            float yv = sZ[r][k];
            val[0] += yv*sW[k][c+0];
            val[1] += yv*sW[k][c+1];
            val[2] += yv*sW[k][c+2];
            val[3] += yv*sW[k][c+3];
        }
#pragma unroll
        for (int j = 0; j < 4; j++) val[j] += bl[c+j];
    } else {
#pragma unroll
        for (int j = 0; j < 4; j++) val[j] = y[j];
    }

#pragma unroll
    for (int j = 0; j < 4; j++) outp[(size_t)row*64 + c + j] = val[j];

    if (csNext) {
        float dN = rsqrtf((float)(pcNext[row] + 1));
        __syncthreads();
#pragma unroll
        for (int j = 0; j < 4; j++) red[r][c+j] = dN*val[j];
        __syncthreads();
        if (tid < 64) {
            float s = 0.f;
#pragma unroll
            for (int rr = 0; rr < 16; rr++) s += red[rr][tid];
            atomicAdd(&csNext[tid], s);
        }
    }
}

// ---------------- host ----------------
static void* sym(const void* s) { void* p = nullptr; cudaGetSymbolAddress(&p, s); return p; }

extern "C" void kernel_launch(void* const* d_in, const int* in_sizes, int n_in,
                              void* d_out, int out_size)
{
    const float* x    = (const float*)d_in[0];
    const float* Aneg = (const float*)d_in[1];
    const float* Apos = (const float*)d_in[2];
    const float* W_l1 = (const float*)d_in[3];  const float* b_l1 = (const float*)d_in[4];
    const float* W_l2 = (const float*)d_in[5];  const float* b_l2 = (const float*)d_in[6];
    const float* W_l3 = (const float*)d_in[7];  const float* b_l3 = (const float*)d_in[8];
    const float* W_g1 = (const float*)d_in[9];  const float* b_g1 = (const float*)d_in[10];
    const float* W_g2 = (const float*)d_in[11]; const float* b_g2 = (const float*)d_in[12];
    const float* W_g3 = (const float*)d_in[13]; const float* b_g3 = (const float*)d_in[14];
    const float* W_g4 = (const float*)d_in[15]; const float* b_g4 = (const float*)d_in[16];
    const float* W_g5 = (const float*)d_in[17]; const float* b_g5 = (const float*)d_in[18];
    const float* W_g6 = (const float*)d_in[19]; const float* b_g6 = (const float*)d_in[20];
    float* out = (float*)d_out;

    uint32_t* apT    = (uint32_t*)sym(g_apT);
    uint32_t* lastT0 = (uint32_t*)sym(g_lastT0);
    uint32_t* lastT1 = (uint32_t*)sym(g_lastT1);
    uint32_t* U      = (uint32_t*)sym(g_U);
    int*   pc   = (int*)sym(g_pc);
    float* cs   = (float*)sym(g_cs);
    float* h1   = (float*)sym(g_h1);
    float* bufA = (float*)sym(g_bufA);
    float* bufB = (float*)sym(g_bufB);

    static cudaStream_t sB = nullptr;
    static cudaEvent_t evF = nullptr;
    static cudaEvent_t ev[6];
    if (!sB) {
        cudaStreamCreateWithFlags(&sB, cudaStreamNonBlocking);
        cudaEventCreateWithFlags(&evF, cudaEventDisableTiming);
        for (int i = 0; i < 6; i++) cudaEventCreateWithFlags(&ev[i], cudaEventDisableTiming);
    }

    // ---- fork: bit chain on side stream (7 launches) ----
    cudaEventRecord(evF, 0);
    cudaStreamWaitEvent(sB, evF, 0);

    zero_kernel<<<48, 256, 0, sB>>>(pc, cs);
    pack_kernel<<<1024, 256, 0, sB>>>(Apos, Aneg, apT, U, lastT0, pc);
    cudaEventRecord(ev[0], sB);

    uint32_t* lt[2] = {lastT0, lastT1};
    for (int s = 1; s <= 5; s++) {
        bitstage_kernel<<<64, 256, 0, sB>>>(lt[(s+1)&1], lt[s&1], apT,
                                            U + (size_t)(s-1)*NN*NW, U + (size_t)s*NN*NW,
                                            pc + s*NN);
        cudaEventRecord(ev[s], sB);
    }

    // ---- float chain on main stream (7 launches) ----
    cudaStreamWaitEvent(0, ev[0], 0);
    gemm_kernel<<<dim3(4,32), 256>>>(x, 512, 512, W_l1, 256, 256, b_l1, h1, 256, pc, cs);

    cudaStreamWaitEvent(0, ev[1], 0);    // needs pc1 for cs1 epilogue
    agg1_kernel<<<256, 512>>>(h1, W_g1, b_g1, pc, U, cs,
                              W_l2, b_l2, pc + NN, cs + 256, bufA);   // -> h2

    // stage 2: x2 -> fused @W_l3 -> h3 ; cs2
    cudaStreamWaitEvent(0, ev[2], 0);
    agg64_kernel<<<128, 256>>>(bufA, 62, W_g2, 62, b_g2,
                               pc + NN, U + (size_t)NN*NW, cs + 256,
                               1.0f, 1, W_l3, b_l3, pc + 2*NN, cs + 2*256, bufB); // -> h3

    // stage 3: x3 ; cs3
    cudaStreamWaitEvent(0, ev[3], 0);
    agg64_kernel<<<128, 256>>>(bufB, 64, W_g3, 64, b_g3,
                               pc + 2*NN, U + (size_t)2*NN*NW, cs + 2*256,
                               0.5f, 1, nullptr, nullptr, pc + 3*NN, cs + 3*256, bufA);

    // stage 4: x4 ; cs4
    cudaStreamWaitEvent(0, ev[4], 0);
    agg64_kernel<<<128, 256>>>(bufA, 64, W_g4, 64, b_g4,
                               pc + 3*NN, U + (size_t)3*NN*NW, cs + 3*256,
                               0.5f, 1, nullptr, nullptr, pc + 4*NN, cs + 4*256, bufB);

    // stage 5: x5 ; cs5
    cudaStreamWaitEvent(0, ev[5], 0);
    agg64_kernel<<<128, 256>>>(bufB, 64, W_g5, 64, b_g5,
                               pc + 4*NN, U + (size_t)4*NN*NW, cs + 4*256,
                               0.25f, 1, nullptr, nullptr, pc + 5*NN, cs + 5*256, bufA);

    // stage 6 (no relu) -> d_out
    agg64_kernel<<<128, 256>>>(bufA, 64, W_g6, 64, b_g6,
                               pc + 5*NN, U + (size_t)5*NN*NW, cs + 5*256,
                               0.25f, 0, nullptr, nullptr, nullptr, nullptr, out);
}

// round 6
// speedup vs baseline: 1.1415x; 1.1008x over previous
#include <cuda_runtime.h>
#include <stdint.h>

#define NN 2048
#define NW 64    // 2048 bits = 64 u32 words
#define CAP 128  // CSC capacity per column of A_pos

// ---------------- device scratch ----------------
__device__ uint32_t g_apT[NN*NW];        // A_pos^T bits
__device__ unsigned short g_idx[NN*CAP]; // CSC: rows k with Ap[k][j]=1, per column j
__device__ int      g_cnt[NN];
__device__ uint32_t g_lastT0[NN*NW];
__device__ uint32_t g_lastT1[NN*NW];
__device__ uint32_t g_U[6*NN*NW];        // union bits per stage (row-major)
__device__ int      g_pc[6*NN];          // popcount per stage
__device__ float    g_cs[6*256];         // colsum of dinv.*h per stage
__device__ float    g_h1[NN*256];
__device__ float    g_bufA[NN*64];
__device__ float    g_bufB[NN*64];

// ---------------- zero pc + cs + cnt ----------------
__global__ void zero_kernel(int* __restrict__ pc, float* __restrict__ cs, int* __restrict__ cnt)
{
    int i = blockIdx.x*blockDim.x + threadIdx.x;
    if (i < 6*NN)  pc[i] = 0;
    if (i < 6*256) cs[i] = 0.f;
    if (i < NN)    cnt[i] = 0;
}

// ---------------- merged pack: A_pos -> apT + CSC ; A_neg -> U0, lastT0, pc0 ----------------
__global__ void pack_kernel(const float* __restrict__ Apos, const float* __restrict__ Aneg,
                            uint32_t* __restrict__ apT,
                            unsigned short* __restrict__ idx, int* __restrict__ cnt,
                            uint32_t* __restrict__ u0, uint32_t* __restrict__ lastT,
                            int* __restrict__ pc0)
{
    int lane = threadIdx.x & 31;
    if (blockIdx.x < 512) {
        int gwarp = blockIdx.x*8 + (threadIdx.x >> 5);
        int ti = gwarp >> 6, tj = gwarp & 63;
        uint32_t tbits = 0;
#pragma unroll
        for (int r = 0; r < 32; r++) {
            float v = Apos[(size_t)(ti*32 + r)*NN + tj*32 + lane];
            tbits |= (v > 0.f ? 1u : 0u) << r;
        }
        int j = tj*32 + lane;
        apT[j*NW + ti] = tbits;
        uint32_t m = tbits;
        while (m) {
            int r = __ffs(m) - 1; m &= (m-1);
            int pos = atomicAdd(&cnt[j], 1);
            if (pos < CAP) idx[j*CAP + pos] = (unsigned short)(ti*32 + r);
        }
    } else {
        int gwarp = (blockIdx.x - 512)*8 + (threadIdx.x >> 5);
        int ti = gwarp >> 6, tj = gwarp & 63;
        uint32_t tbits = 0, rw = 0;
#pragma unroll
        for (int r = 0; r < 32; r++) {
            float v = Aneg[(size_t)(ti*32 + r)*NN + tj*32 + lane];
            uint32_t b = (v > 0.f) ? 1u : 0u;
            tbits |= b << r;
            uint32_t m = __ballot_sync(0xffffffffu, b);
            if (lane == r) rw = m;
        }
        u0[(ti*32 + lane)*NW + tj] = rw;
        atomicAdd(&pc0[ti*32 + lane], __popc(rw));
        lastT[(tj*32 + lane)*NW + ti] = tbits;
    }
}

// ---------------- fused bit stage v2: CSC expand (uint4) + transpose + OR + pc ----------------
// grid (64, 2): blockIdx.x = jtile (32 columns), blockIdx.y = wtile (8 uint4 = 32 words = 1024 rows)
__global__ void __launch_bounds__(256) bitstage_kernel(
        const uint4* __restrict__ lastOld4, uint4* __restrict__ lastNew4,
        const unsigned short* __restrict__ idx, const int* __restrict__ cnt,
        const uint32_t* __restrict__ uPrev, uint32_t* __restrict__ uCur,
        int* __restrict__ pcCur)
{
    __shared__ uint32_t sN[32][33];
    int jt = blockIdx.x, wt = blockIdx.y;
    int tid = threadIdx.x;
    int jl = tid >> 3;          // 0..31
    int w4l = tid & 7;          // 0..7
    int j = jt*32 + jl;
    int w4 = wt*8 + w4l;        // uint4 index within row (0..15)

    int c = cnt[j]; if (c > CAP) c = CAP;
    const unsigned short* lst = idx + j*CAP;
    uint4 acc = make_uint4(0u,0u,0u,0u);
    int t = 0;
    for (; t + 4 <= c; t += 4) {
        int k0 = lst[t], k1 = lst[t+1], k2 = lst[t+2], k3 = lst[t+3];
        uint4 v0 = lastOld4[k0*16 + w4];
        uint4 v1 = lastOld4[k1*16 + w4];
        uint4 v2 = lastOld4[k2*16 + w4];
        uint4 v3 = lastOld4[k3*16 + w4];
        acc.x |= v0.x | v1.x | v2.x | v3.x;
        acc.y |= v0.y | v1.y | v2.y | v3.y;
        acc.z |= v0.z | v1.z | v2.z | v3.z;
        acc.w |= v0.w | v1.w | v2.w | v3.w;
    }
    for (; t < c; t++) {
        uint4 v = lastOld4[lst[t]*16 + w4];
        acc.x |= v.x; acc.y |= v.y; acc.z |= v.z; acc.w |= v.w;
    }
    lastNew4[j*16 + w4] = acc;
    sN[jl][w4l*4 + 0] = acc.x;
    sN[jl][w4l*4 + 1] = acc.y;
    sN[jl][w4l*4 + 2] = acc.z;
    sN[jl][w4l*4 + 3] = acc.w;
    __syncthreads();

    int warp = tid >> 5, lane = tid & 31;
    for (int wl = warp; wl < 32; wl += 8) {
        uint32_t v = sN[lane][wl];
        uint32_t ow = 0;
#pragma unroll
        for (int ib = 0; ib < 32; ib++) {
            uint32_t mm = __ballot_sync(0xffffffffu, (v >> ib) & 1u);
            if (lane == ib) ow = mm;
        }
        int i = (wt*32 + wl)*32 + lane;
        uint32_t merged = uPrev[i*NW + jt] | ow;
        uCur[i*NW + jt] = merged;
        atomicAdd(&pcCur[i], __popc(merged));
    }
}

// ---------------- specialized gemm1: h1[2048x256] = x[2048x512] @ W_l1 + b_l1 ; cs0 ----------------
// tile 32(M) x 64(N), grid (4, 64), 256 threads
__global__ void __launch_bounds__(256) gemm1_kernel(
        const float* __restrict__ A,      // 2048 x 512
        const float* __restrict__ W,      // 512 x 256
        const float* __restrict__ bias,
        float* __restrict__ C,            // 2048 x 256
        const int* __restrict__ pcS,
        float* __restrict__ cs)
{
    __shared__ __align__(16) float As[16][34];
    __shared__ __align__(16) float Ws[16][64];
    __shared__ float red[16][64];
    int tid = threadIdx.x;
    int tx = tid & 15, ty = tid >> 4;
    int rowBase = blockIdx.y*32, colBase = blockIdx.x*64;
    float acc[2][4] = {};
    int mA  = tid >> 3, kk2 = (tid & 7)*2;
    int kkW = tid >> 4, cW  = (tid & 15)*4;

    for (int k0 = 0; k0 < 512; k0 += 16) {
        float2 a2 = *(const float2*)(A + (size_t)(rowBase + mA)*512 + k0 + kk2);
        As[kk2][mA]   = a2.x;
        As[kk2+1][mA] = a2.y;
        *(float4*)&Ws[kkW][cW] = *(const float4*)(W + (size_t)(k0 + kkW)*256 + colBase + cW);
        __syncthreads();
#pragma unroll
        for (int kk = 0; kk < 16; kk++) {
            float2 av = *(const float2*)&As[kk][ty*2];
            float4 bv = *(const float4*)&Ws[kk][tx*4];
            acc[0][0] += av.x*bv.x; acc[0][1] += av.x*bv.y;
            acc[0][2] += av.x*bv.z; acc[0][3] += av.x*bv.w;
            acc[1][0] += av.y*bv.x; acc[1][1] += av.y*bv.y;
            acc[1][2] += av.y*bv.z; acc[1][3] += av.y*bv.w;
        }
        __syncthreads();
    }

    float p[4] = {0.f, 0.f, 0.f, 0.f};
#pragma unroll
    for (int a = 0; a < 2; a++) {
        int row = rowBase + ty*2 + a;
        float di = rsqrtf((float)(pcS[row] + 1));
#pragma unroll
        for (int b = 0; b < 4; b++) {
            int col = colBase + tx*4 + b;
            float val = acc[a][b] + bias[col];
            C[(size_t)row*256 + col] = val;
            p[b] += di * val;
        }
    }
#pragma unroll
    for (int b = 0; b < 4; b++) red[ty][tx*4 + b] = p[b];
    __syncthreads();
    if (tid < 64) {
        float s = 0.f;
#pragma unroll
        for (int t = 0; t < 16; t++) s += red[t][tid];
        atomicAdd(&cs[colBase + tid], s);
    }
}

// ---------------- stage 1: agg(F=256) + z@Wg1 + relu-residual + fused x1@W_l2 -> h2, cs1 ----------------
__global__ void __launch_bounds__(512) agg1_kernel(
        const float* __restrict__ h,      // h1 2048x256
        const float* __restrict__ Wg,     // W_g1 256x256
        const float* __restrict__ bg,
        const int* __restrict__ pcS,      // pc0
        const uint32_t* __restrict__ u,   // union0
        const float* __restrict__ cs,     // cs0
        const float* __restrict__ Wl,     // W_l2 256x62
        const float* __restrict__ bl,     // b_l2
        const int* __restrict__ pcNext,   // pc1
        float* __restrict__ csNext,       // cs1
        float* __restrict__ outp)         // h2 2048x64 (cols 62,63 = 0)
{
    __shared__ float sDinv[NN];
    __shared__ uint32_t sU[8][64];
    __shared__ float sZ[8][256];
    __shared__ float sX[8][256];
    __shared__ float sRed[8][64];
    int tid = threadIdx.x;
    int row0 = blockIdx.x*8;

    for (int t = tid; t < NN; t += 512) sDinv[t] = rsqrtf((float)(pcS[t] + 1));
    { int r = tid >> 6, c = tid & 63; sU[r][c] = u[(row0 + r)*NW + c]; }
    __syncthreads();

    {
        int lane = tid & 63, grp = tid >> 6;
        int row = row0 + grp;
        int f = lane*4;
        bool comp = pcS[row] > 1024;
        float4 acc = make_float4(0.f,0.f,0.f,0.f);
        for (int w2 = 0; w2 < NW; w2++) {
            uint32_t m = sU[grp][w2];
            if (comp) m = ~m;
            int kb = w2*32;
            while (m) {
                int bq = __ffs(m) - 1; m &= (m-1);
                int k = kb + bq;
                float4 v = *(const float4*)(h + (size_t)k*256 + f);
                float d = sDinv[k];
                acc.x += d*v.x; acc.y += d*v.y; acc.z += d*v.z; acc.w += d*v.w;
            }
        }
        if (comp) {
            float4 c4 = *(const float4*)(cs + f);
            acc.x = c4.x - acc.x; acc.y = c4.y - acc.y;
            acc.z = c4.z - acc.z; acc.w = c4.w - acc.w;
        }
        float di = sDinv[row];
        float4 hv = *(const float4*)(h + (size_t)row*256 + f);
        sZ[grp][f+0] = di*(acc.x + di*hv.x);
        sZ[grp][f+1] = di*(acc.y + di*hv.y);
        sZ[grp][f+2] = di*(acc.z + di*hv.z);
        sZ[grp][f+3] = di*(acc.w + di*hv.w);
    }
    __syncthreads();

    {
        int r = tid >> 6;
        int c = (tid & 63)*4;
        int row = row0 + r;
        float a0=0.f, a1=0.f, a2=0.f, a3=0.f;
#pragma unroll 4
        for (int k = 0; k < 256; k++) {
            float zv = sZ[r][k];
            float4 wv = *(const float4*)(Wg + (size_t)k*256 + c);
            a0 += zv*wv.x; a1 += zv*wv.y; a2 += zv*wv.z; a3 += zv*wv.w;
        }
        float4 b4 = *(const float4*)(bg + c);
        float4 hv = *(const float4*)(h + (size_t)row*256 + c);
        sX[r][c+0] = hv.x + fmaxf(a0 + b4.x, 0.f);
        sX[r][c+1] = hv.y + fmaxf(a1 + b4.y, 0.f);
        sX[r][c+2] = hv.z + fmaxf(a2 + b4.z, 0.f);
        sX[r][c+3] = hv.w + fmaxf(a3 + b4.w, 0.f);
    }
    __syncthreads();

    {
        int r = tid >> 6;
        int cc = tid & 63;
        int row = row0 + r;
        float val = 0.f;
        if (cc < 62) {
            float a = 0.f;
#pragma unroll 4
            for (int k = 0; k < 256; k++)
                a += sX[r][k] * Wl[(size_t)k*62 + cc];
            val = a + bl[cc];
        }
        outp[(size_t)row*64 + cc] = val;
        float dN = rsqrtf((float)(pcNext[row] + 1));
        sRed[r][cc] = dN*val;
    }
    __syncthreads();
    if (tid < 64) {
        float s = 0.f;
#pragma unroll
        for (int r = 0; r < 8; r++) s += sRed[r][tid];
        atomicAdd(&csNext[tid], s);
    }
}

// ---------------- stages 2-6: agg(F<=64) + z@Wg + residual [+ fused @Wl] + optional csNext ----------------
__global__ void __launch_bounds__(256) agg64_kernel(
        const float* __restrict__ h, int NcIn,
        const float* __restrict__ Wg, int ldwg,
        const float* __restrict__ bg,
        const int* __restrict__ pcS,
        const uint32_t* __restrict__ u,
        const float* __restrict__ cs,
        float wscale, int doRelu,
        const float* __restrict__ Wl,
        const float* __restrict__ bl,
        const int* __restrict__ pcNext,
        float* __restrict__ csNext,
        float* __restrict__ outp)
{
    __shared__ float sDinv[NN];
    __shared__ uint32_t sU[16][64];
    __shared__ float sW[64][64];
    __shared__ float sZ[16][64];
    __shared__ float red[16][64];
    int tid = threadIdx.x;
    int row0 = blockIdx.x*16;

    for (int t = tid; t < NN; t += 256) sDinv[t] = rsqrtf((float)(pcS[t] + 1));
    for (int t = tid; t < 16*64; t += 256) {
        int r = t >> 6, c = t & 63;
        sU[r][c] = u[(row0 + r)*NW + c];
    }
    for (int t = tid; t < 64*64; t += 256) {
        int k = t >> 6, c = t & 63;
        sW[k][c] = (k < NcIn && c < NcIn) ? Wg[(size_t)k*ldwg + c] : 0.f;
    }
    __syncthreads();

    {
        int lane = tid & 15, grp = tid >> 4;
        int row = row0 + grp;
        int f = lane*4;
        bool comp = pcS[row] > 1024;
        float4 acc = make_float4(0.f,0.f,0.f,0.f);
        for (int w2 = 0; w2 < NW; w2++) {
            uint32_t m = sU[grp][w2];
            if (comp) m = ~m;
            int kb = w2*32;
            while (m) {
                int bq = __ffs(m) - 1; m &= (m-1);
                int k = kb + bq;
                float4 v = *(const float4*)(h + (size_t)k*64 + f);
                float d = sDinv[k];
                acc.x += d*v.x; acc.y += d*v.y; acc.z += d*v.z; acc.w += d*v.w;
            }
        }
        if (comp) {
            float4 c4 = *(const float4*)(cs + f);
            acc.x = c4.x - acc.x; acc.y = c4.y - acc.y;
            acc.z = c4.z - acc.z; acc.w = c4.w - acc.w;
        }
        float di = sDinv[row];
        float4 hv = *(const float4*)(h + (size_t)row*64 + f);
        sZ[grp][f+0] = di*(acc.x + di*hv.x);
        sZ[grp][f+1] = di*(acc.y + di*hv.y);
        sZ[grp][f+2] = di*(acc.z + di*hv.z);
        sZ[grp][f+3] = di*(acc.w + di*hv.w);
    }
    __syncthreads();

    int r = tid >> 4;
    int c = (tid & 15)*4;
    int row = row0 + r;
    float y[4] = {0.f, 0.f, 0.f, 0.f};
#pragma unroll 8
    for (int k = 0; k < 64; k++) {
        float zv = sZ[r][k];
        y[0] += zv*sW[k][c+0];
        y[1] += zv*sW[k][c+1];
        y[2] += zv*sW[k][c+2];
        y[3] += zv*sW[k][c+3];
    }
#pragma unroll
    for (int j = 0; j < 4; j++) {
        int cc = c + j;
        float b = (cc < NcIn) ? bg[cc] : 0.f;
        float v = y[j] + b;
        if (doRelu) v = fmaxf(v, 0.f);
        y[j] = h[(size_t)row*64 + cc] + wscale*v;
    }

    float val[4];
    if (Wl) {
        __syncthreads();
#pragma unroll
        for (int j = 0; j < 4; j++) sZ[r][c+j] = y[j];
        for (int t = tid; t < 64*64; t += 256) {
            int k = t >> 6, cc2 = t & 63;
            sW[k][cc2] = (k < NcIn) ? Wl[(size_t)k*64 + cc2] : 0.f;
        }
        __syncthreads();
#pragma unroll
        for (int j = 0; j < 4; j++) val[j] = 0.f;
#pragma unroll 8
        for (int k = 0; k < 64; k++) {
            float yv = sZ[r][k];
            val[0] += yv*sW[k][c+0];
            val[1] += yv*sW[k][c+1];
            val[2] += yv*sW[k][c+2];
            val[3] += yv*sW[k][c+3];
        }
#pragma unroll
        for (int j = 0; j < 4; j++) val[j] += bl[c+j];
    } else {
#pragma unroll
        for (int j = 0; j < 4; j++) val[j] = y[j];
    }

#pragma unroll
    for (int j = 0; j < 4; j++) outp[(size_t)row*64 + c + j] = val[j];

    if (csNext) {
        float dN = rsqrtf((float)(pcNext[row] + 1));
        __syncthreads();
#pragma unroll
        for (int j = 0; j < 4; j++) red[r][c+j] = dN*val[j];
        __syncthreads();
        if (tid < 64) {
            float s = 0.f;
#pragma unroll
            for (int rr = 0; rr < 16; rr++) s += red[rr][tid];
            atomicAdd(&csNext[tid], s);
        }
    }
}

// ---------------- host ----------------
static void* sym(const void* s) { void* p = nullptr; cudaGetSymbolAddress(&p, s); return p; }

extern "C" void kernel_launch(void* const* d_in, const int* in_sizes, int n_in,
                              void* d_out, int out_size)
{
    const float* x    = (const float*)d_in[0];
    const float* Aneg = (const float*)d_in[1];
    const float* Apos = (const float*)d_in[2];
    const float* W_l1 = (const float*)d_in[3];  const float* b_l1 = (const float*)d_in[4];
    const float* W_l2 = (const float*)d_in[5];  const float* b_l2 = (const float*)d_in[6];
    const float* W_l3 = (const float*)d_in[7];  const float* b_l3 = (const float*)d_in[8];
    const float* W_g1 = (const float*)d_in[9];  const float* b_g1 = (const float*)d_in[10];
    const float* W_g2 = (const float*)d_in[11]; const float* b_g2 = (const float*)d_in[12];
    const float* W_g3 = (const float*)d_in[13]; const float* b_g3 = (const float*)d_in[14];
    const float* W_g4 = (const float*)d_in[15]; const float* b_g4 = (const float*)d_in[16];
    const float* W_g5 = (const float*)d_in[17]; const float* b_g5 = (const float*)d_in[18];
    const float* W_g6 = (const float*)d_in[19]; const float* b_g6 = (const float*)d_in[20];
    float* out = (float*)d_out;

    uint32_t* apT    = (uint32_t*)sym(g_apT);
    unsigned short* idx = (unsigned short*)sym(g_idx);
    int*      cnt    = (int*)sym(g_cnt);
    uint32_t* lastT0 = (uint32_t*)sym(g_lastT0);
    uint32_t* lastT1 = (uint32_t*)sym(g_lastT1);
    uint32_t* U      = (uint32_t*)sym(g_U);
    int*   pc   = (int*)sym(g_pc);
    float* cs   = (float*)sym(g_cs);
    float* h1   = (float*)sym(g_h1);
    float* bufA = (float*)sym(g_bufA);
    float* bufB = (float*)sym(g_bufB);

    static cudaStream_t sB = nullptr;
    static cudaEvent_t evF = nullptr;
    static cudaEvent_t ev[6];
    if (!sB) {
        cudaStreamCreateWithFlags(&sB, cudaStreamNonBlocking);
        cudaEventCreateWithFlags(&evF, cudaEventDisableTiming);
        for (int i = 0; i < 6; i++) cudaEventCreateWithFlags(&ev[i], cudaEventDisableTiming);
    }

    // ---- fork: bit chain on side stream ----
    cudaEventRecord(evF, 0);
    cudaStreamWaitEvent(sB, evF, 0);

    zero_kernel<<<48, 256, 0, sB>>>(pc, cs, cnt);
    pack_kernel<<<1024, 256, 0, sB>>>(Apos, Aneg, apT, idx, cnt, U, lastT0, pc);
    cudaEventRecord(ev[0], sB);

    uint32_t* lt[2] = {lastT0, lastT1};
    for (int s = 1; s <= 5; s++) {
        bitstage_kernel<<<dim3(64,2), 256, 0, sB>>>(
            (const uint4*)lt[(s+1)&1], (uint4*)lt[s&1], idx, cnt,
            U + (size_t)(s-1)*NN*NW, U + (size_t)s*NN*NW, pc + s*NN);
        cudaEventRecord(ev[s], sB);
    }

    // ---- float chain on main stream ----
    cudaStreamWaitEvent(0, ev[0], 0);
    gemm1_kernel<<<dim3(4,64), 256>>>(x, W_l1, b_l1, h1, pc, cs);

    cudaStreamWaitEvent(0, ev[1], 0);
    agg1_kernel<<<256, 512>>>(h1, W_g1, b_g1, pc, U, cs,
                              W_l2, b_l2, pc + NN, cs + 256, bufA);   // -> h2

    cudaStreamWaitEvent(0, ev[2], 0);
    agg64_kernel<<<128, 256>>>(bufA, 62, W_g2, 62, b_g2,
                               pc + NN, U + (size_t)NN*NW, cs + 256,
                               1.0f, 1, W_l3, b_l3, pc + 2*NN, cs + 2*256, bufB); // -> h3

    cudaStreamWaitEvent(0, ev[3], 0);
    agg64_kernel<<<128, 256>>>(bufB, 64, W_g3, 64, b_g3,
                               pc + 2*NN, U + (size_t)2*NN*NW, cs + 2*256,
                               0.5f, 1, nullptr, nullptr, pc + 3*NN, cs + 3*256, bufA);

    cudaStreamWaitEvent(0, ev[4], 0);
    agg64_kernel<<<128, 256>>>(bufA, 64, W_g4, 64, b_g4,
                               pc + 3*NN, U + (size_t)3*NN*NW, cs + 3*256,
                               0.5f, 1, nullptr, nullptr, pc + 4*NN, cs + 4*256, bufB);

    cudaStreamWaitEvent(0, ev[5], 0);
    agg64_kernel<<<128, 256>>>(bufB, 64, W_g5, 64, b_g5,
                               pc + 4*NN, U + (size_t)4*NN*NW, cs + 4*256,
                               0.25f, 1, nullptr, nullptr, pc + 5*NN, cs + 5*256, bufA);

    agg64_kernel<<<128, 256>>>(bufA, 64, W_g6, 64, b_g6,
                               pc + 5*NN, U + (size_t)5*NN*NW, cs + 5*256,
                               0.25f, 0, nullptr, nullptr, nullptr, nullptr, out);
}

// round 7
// speedup vs baseline: 1.2975x; 1.1367x over previous
#include <cuda_runtime.h>
#include <stdint.h>

#define NN 2048
#define NW 64    // 2048 bits = 64 u32 words
#define CAP 128  // CSC capacity per column of A_pos
#define NBLK 256
#define NTHR 256

// ---------------- device scratch (single-writer-then-read buffers) ----------------
__device__ __align__(16) uint32_t g_apT[NN*NW];
__device__ unsigned short g_idx[NN*CAP];
__device__ int      g_cnt[NN];
__device__ __align__(16) uint32_t g_lastT[6][NN*NW]; // [0]=A_neg^T, [s]=s-hop expansion
__device__ __align__(16) uint32_t g_U[6][NN*NW];     // union bits per stage (row-major)
__device__ int      g_pc[6*NN];
__device__ float    g_cs[6*256];
__device__ __align__(16) float g_h1[NN*256];
__device__ __align__(16) float g_xb[5][NN*64];       // h2, h3, x3, x4, x5
__device__ int          g_barCount = 0;
__device__ volatile int g_barGen   = 0;

// ---------------- software grid barrier ----------------
__device__ __forceinline__ void gsync()
{
    __threadfence();
    __syncthreads();
    if (threadIdx.x == 0) {
        int gen = g_barGen;
        if (atomicAdd(&g_barCount, 1) == (int)gridDim.x - 1) {
            g_barCount = 0;
            __threadfence();
            g_barGen = gen + 1;
        } else {
            while (g_barGen == gen) { __nanosleep(32); }
        }
    }
    __syncthreads();
}

// ---------------- phase units (smem passed from kernel) ----------------
__device__ void pack_unit(int u, const float* __restrict__ Apos, const float* __restrict__ Aneg, int tid)
{
    int lane = tid & 31;
    if (u < 512) {
        int gwarp = u*8 + (tid >> 5);
        int ti = gwarp >> 6, tj = gwarp & 63;
        uint32_t tbits = 0;
#pragma unroll
        for (int r = 0; r < 32; r++) {
            float v = Apos[(size_t)(ti*32 + r)*NN + tj*32 + lane];
            tbits |= (v > 0.f ? 1u : 0u) << r;
        }
        int j = tj*32 + lane;
        g_apT[j*NW + ti] = tbits;
        uint32_t m = tbits;
        while (m) {
            int r = __ffs(m) - 1; m &= (m-1);
            int pos = atomicAdd(&g_cnt[j], 1);
            if (pos < CAP) g_idx[j*CAP + pos] = (unsigned short)(ti*32 + r);
        }
    } else {
        int gwarp = (u - 512)*8 + (tid >> 5);
        int ti = gwarp >> 6, tj = gwarp & 63;
        uint32_t tbits = 0, rw = 0;
#pragma unroll
        for (int r = 0; r < 32; r++) {
            float v = Aneg[(size_t)(ti*32 + r)*NN + tj*32 + lane];
            uint32_t b = (v > 0.f) ? 1u : 0u;
            tbits |= b << r;
            uint32_t m = __ballot_sync(0xffffffffu, b);
            if (lane == r) rw = m;
        }
        g_U[0][(ti*32 + lane)*NW + tj] = rw;
        atomicAdd(&g_pc[ti*32 + lane], __popc(rw));
        g_lastT[0][(tj*32 + lane)*NW + ti] = tbits;
    }
}

// unit v in [0,128): jt = v&63 (32 columns), wt = v>>6 (8 uint4 = 1024 rows)
__device__ void bitstage_unit(int v, const uint4* __restrict__ lastOld4, uint4* __restrict__ lastNew4,
                              const uint32_t* __restrict__ uPrev, uint32_t* __restrict__ uCur,
                              int* __restrict__ pcCur, int tid, float* smemf)
{
    uint32_t (*sN)[33] = (uint32_t(*)[33])smemf;
    __syncthreads();
    int jt = v & 63, wt = v >> 6;
    int jl = tid >> 3;
    int w4l = tid & 7;
    int j = jt*32 + jl;
    int w4 = wt*8 + w4l;

    int c = g_cnt[j]; if (c > CAP) c = CAP;
    const unsigned short* lst = g_idx + j*CAP;
    uint4 acc = make_uint4(0u,0u,0u,0u);
    int t = 0;
    for (; t + 4 <= c; t += 4) {
        int k0 = lst[t], k1 = lst[t+1], k2 = lst[t+2], k3 = lst[t+3];
        uint4 v0 = lastOld4[k0*16 + w4];
        uint4 v1 = lastOld4[k1*16 + w4];
        uint4 v2 = lastOld4[k2*16 + w4];
        uint4 v3 = lastOld4[k3*16 + w4];
        acc.x |= v0.x | v1.x | v2.x | v3.x;
        acc.y |= v0.y | v1.y | v2.y | v3.y;
        acc.z |= v0.z | v1.z | v2.z | v3.z;
        acc.w |= v0.w | v1.w | v2.w | v3.w;
    }
    for (; t < c; t++) {
        uint4 vv = lastOld4[lst[t]*16 + w4];
        acc.x |= vv.x; acc.y |= vv.y; acc.z |= vv.z; acc.w |= vv.w;
    }
    lastNew4[j*16 + w4] = acc;
    sN[jl][w4l*4 + 0] = acc.x;
    sN[jl][w4l*4 + 1] = acc.y;
    sN[jl][w4l*4 + 2] = acc.z;
    sN[jl][w4l*4 + 3] = acc.w;
    __syncthreads();

    int warp = tid >> 5, lane = tid & 31;
    for (int wl = warp; wl < 32; wl += 8) {
        uint32_t v2 = sN[lane][wl];
        uint32_t ow = 0;
#pragma unroll
        for (int ib = 0; ib < 32; ib++) {
            uint32_t mm = __ballot_sync(0xffffffffu, (v2 >> ib) & 1u);
            if (lane == ib) ow = mm;
        }
        int i = (wt*32 + wl)*32 + lane;
        uint32_t merged = uPrev[i*NW + jt] | ow;
        uCur[i*NW + jt] = merged;
        atomicAdd(&pcCur[i], __popc(merged));
    }
}

// unit u in [0,256): bx = u&3 (64 cols), by = u>>2 (32 rows)
__device__ void gemm1_unit(int u, const float* __restrict__ A, const float* __restrict__ W,
                           const float* __restrict__ bias, int tid, float* smemf)
{
    float (*As)[34]  = (float(*)[34])smemf;                 // 544
    float (*Ws)[64]  = (float(*)[64])(smemf + 544);         // 1024
    float (*red)[64] = (float(*)[64])(smemf + 544 + 1024);  // 1024
    __syncthreads();
    int tx = tid & 15, ty = tid >> 4;
    int rowBase = (u >> 2)*32, colBase = (u & 3)*64;
    float acc[2][4] = {};
    int mA  = tid >> 3, kk2 = (tid & 7)*2;
    int kkW = tid >> 4, cW  = (tid & 15)*4;

    for (int k0 = 0; k0 < 512; k0 += 16) {
        float2 a2 = *(const float2*)(A + (size_t)(rowBase + mA)*512 + k0 + kk2);
        As[kk2][mA]   = a2.x;
        As[kk2+1][mA] = a2.y;
        *(float4*)&Ws[kkW][cW] = *(const float4*)(W + (size_t)(k0 + kkW)*256 + colBase + cW);
        __syncthreads();
#pragma unroll
        for (int kk = 0; kk < 16; kk++) {
            float2 av = *(const float2*)&As[kk][ty*2];
            float4 bv = *(const float4*)&Ws[kk][tx*4];
            acc[0][0] += av.x*bv.x; acc[0][1] += av.x*bv.y;
            acc[0][2] += av.x*bv.z; acc[0][3] += av.x*bv.w;
            acc[1][0] += av.y*bv.x; acc[1][1] += av.y*bv.y;
            acc[1][2] += av.y*bv.z; acc[1][3] += av.y*bv.w;
        }
        __syncthreads();
    }

    float p[4] = {0.f, 0.f, 0.f, 0.f};
#pragma unroll
    for (int a = 0; a < 2; a++) {
        int row = rowBase + ty*2 + a;
        float di = rsqrtf((float)(g_pc[row] + 1));
#pragma unroll
        for (int b = 0; b < 4; b++) {
            int col = colBase + tx*4 + b;
            float val = acc[a][b] + bias[col];
            g_h1[(size_t)row*256 + col] = val;
            p[b] += di * val;
        }
    }
#pragma unroll
    for (int b = 0; b < 4; b++) red[ty][tx*4 + b] = p[b];
    __syncthreads();
    if (tid < 64) {
        float s = 0.f;
#pragma unroll
        for (int t = 0; t < 16; t++) s += red[t][tid];
        atomicAdd(&g_cs[colBase + tid], s);
    }
}

// unit u in [0,512): 4 rows each. agg(F=256) + z@Wg1 + relu residual + fused x1@W_l2 -> h2, cs1
__device__ void agg1_unit(int u, const float* __restrict__ Wg, const float* __restrict__ bg,
                          const float* __restrict__ Wl, const float* __restrict__ bl,
                          int tid, float* smemf)
{
    float*    sDinv = smemf;                            // 2048
    uint32_t (*sU)[64] = (uint32_t(*)[64])(smemf + 2048); // 256
    float (*sZ)[256] = (float(*)[256])(smemf + 2304);   // 1024
    float (*sX)[256] = (float(*)[256])(smemf + 3328);   // 1024
    float (*sRed)[64] = (float(*)[64])(smemf + 4352);   // 256
    __syncthreads();
    int row0 = u*4;
    const float* h = g_h1;

    for (int t = tid; t < NN; t += NTHR) sDinv[t] = rsqrtf((float)(g_pc[t] + 1));
    { int r = tid >> 6, c = tid & 63; sU[r][c] = g_U[0][(row0 + r)*NW + c]; }
    __syncthreads();

    // P1: z
    {
        int lane = tid & 63, grp = tid >> 6;
        int row = row0 + grp;
        int f = lane*4;
        bool comp = g_pc[row] > 1024;
        float4 acc = make_float4(0.f,0.f,0.f,0.f);
        for (int w2 = 0; w2 < NW; w2++) {
            uint32_t m = sU[grp][w2];
            if (comp) m = ~m;
            int kb = w2*32;
            while (m) {
                int bq = __ffs(m) - 1; m &= (m-1);
                int k = kb + bq;
                float4 v = *(const float4*)(h + (size_t)k*256 + f);
                float d = sDinv[k];
                acc.x += d*v.x; acc.y += d*v.y; acc.z += d*v.z; acc.w += d*v.w;
            }
        }
        if (comp) {
            float4 c4 = *(const float4*)(g_cs + f);
            acc.x = c4.x - acc.x; acc.y = c4.y - acc.y;
            acc.z = c4.z - acc.z; acc.w = c4.w - acc.w;
        }
        float di = sDinv[row];
        float4 hv = *(const float4*)(h + (size_t)row*256 + f);
        sZ[grp][f+0] = di*(acc.x + di*hv.x);
        sZ[grp][f+1] = di*(acc.y + di*hv.y);
        sZ[grp][f+2] = di*(acc.z + di*hv.z);
        sZ[grp][f+3] = di*(acc.w + di*hv.w);
    }
    __syncthreads();

    // P2: x1 = h1 + relu(z@Wg + bg)
    {
        int r = tid >> 6;
        int c = (tid & 63)*4;
        int row = row0 + r;
        float a0=0.f, a1=0.f, a2=0.f, a3=0.f;
#pragma unroll 4
        for (int k = 0; k < 256; k++) {
            float zv = sZ[r][k];
            float4 wv = *(const float4*)(Wg + (size_t)k*256 + c);
            a0 += zv*wv.x; a1 += zv*wv.y; a2 += zv*wv.z; a3 += zv*wv.w;
        }
        float4 b4 = *(const float4*)(bg + c);
        float4 hv = *(const float4*)(h + (size_t)row*256 + c);
        sX[r][c+0] = hv.x + fmaxf(a0 + b4.x, 0.f);
        sX[r][c+1] = hv.y + fmaxf(a1 + b4.y, 0.f);
        sX[r][c+2] = hv.z + fmaxf(a2 + b4.z, 0.f);
        sX[r][c+3] = hv.w + fmaxf(a3 + b4.w, 0.f);
    }
    __syncthreads();

    // P3: h2 = x1@W_l2 + b_l2 (62 cols, pad 64); cs1 += dinv1*h2
    {
        int r = tid >> 6;
        int cc = tid & 63;
        int row = row0 + r;
        float val = 0.f;
        if (cc < 62) {
            float a = 0.f;
#pragma unroll 4
            for (int k = 0; k < 256; k++)
                a += sX[r][k] * Wl[(size_t)k*62 + cc];
            val = a + bl[cc];
        }
        g_xb[0][(size_t)row*64 + cc] = val;
        float dN = rsqrtf((float)(g_pc[NN + row] + 1));
        sRed[r][cc] = dN*val;
    }
    __syncthreads();
    if (tid < 64) {
        float s = 0.f;
#pragma unroll
        for (int r = 0; r < 4; r++) s += sRed[r][tid];
        atomicAdd(&g_cs[256 + tid], s);
    }
}

// unit u in [0,128): 16 rows. stages 2..6
__device__ void agg64_unit(int u, const float* __restrict__ h, int NcIn,
                           const float* __restrict__ Wg, int ldwg, const float* __restrict__ bg,
                           const int* __restrict__ pcS, const uint32_t* __restrict__ uBits,
                           const float* __restrict__ cs, float wscale, int doRelu,
                           const float* __restrict__ Wl, const float* __restrict__ bl,
                           const int* __restrict__ pcNext, float* __restrict__ csNext,
                           float* __restrict__ outp, int tid, float* smemf)
{
    float* sDinv = smemf;                                  // 2048
    uint32_t (*sU)[64] = (uint32_t(*)[64])(smemf + 2048);  // 1024
    float (*sW)[64] = (float(*)[64])(smemf + 3072);        // 4096
    float (*sZ)[64] = (float(*)[64])(smemf + 7168);        // 1024
    float (*red)[64] = (float(*)[64])(smemf + 8192);       // 1024
    __syncthreads();
    int row0 = u*16;

    for (int t = tid; t < NN; t += NTHR) sDinv[t] = rsqrtf((float)(pcS[t] + 1));
    for (int t = tid; t < 16*64; t += NTHR) {
        int r = t >> 6, c = t & 63;
        sU[r][c] = uBits[(row0 + r)*NW + c];
    }
    for (int t = tid; t < 64*64; t += NTHR) {
        int k = t >> 6, c = t & 63;
        sW[k][c] = (k < NcIn && c < NcIn) ? Wg[(size_t)k*ldwg + c] : 0.f;
    }
    __syncthreads();

    {
        int lane = tid & 15, grp = tid >> 4;
        int row = row0 + grp;
        int f = lane*4;
        bool comp = pcS[row] > 1024;
        float4 acc = make_float4(0.f,0.f,0.f,0.f);
        for (int w2 = 0; w2 < NW; w2++) {
            uint32_t m = sU[grp][w2];
            if (comp) m = ~m;
            int kb = w2*32;
            while (m) {
                int bq = __ffs(m) - 1; m &= (m-1);
                int k = kb + bq;
                float4 v = *(const float4*)(h + (size_t)k*64 + f);
                float d = sDinv[k];
                acc.x += d*v.x; acc.y += d*v.y; acc.z += d*v.z; acc.w += d*v.w;
            }
        }
        if (comp) {
            float4 c4 = *(const float4*)(cs + f);
            acc.x = c4.x - acc.x; acc.y = c4.y - acc.y;
            acc.z = c4.z - acc.z; acc.w = c4.w - acc.w;
        }
        float di = sDinv[row];
        float4 hv = *(const float4*)(h + (size_t)row*64 + f);
        sZ[grp][f+0] = di*(acc.x + di*hv.x);
        sZ[grp][f+1] = di*(acc.y + di*hv.y);
        sZ[grp][f+2] = di*(acc.z + di*hv.z);
        sZ[grp][f+3] = di*(acc.w + di*hv.w);
    }
    __syncthreads();

    int r = tid >> 4;
    int c = (tid & 15)*4;
    int row = row0 + r;
    float y[4] = {0.f, 0.f, 0.f, 0.f};
#pragma unroll 8
    for (int k = 0; k < 64; k++) {
        float zv = sZ[r][k];
        y[0] += zv*sW[k][c+0];
        y[1] += zv*sW[k][c+1];
        y[2] += zv*sW[k][c+2];
        y[3] += zv*sW[k][c+3];
    }
#pragma unroll
    for (int j = 0; j < 4; j++) {
        int cc = c + j;
        float b = (cc < NcIn) ? bg[cc] : 0.f;
        float v = y[j] + b;
        if (doRelu) v = fmaxf(v, 0.f);
        y[j] = h[(size_t)row*64 + cc] + wscale*v;
    }

    float val[4];
    if (Wl) {
        __syncthreads();
#pragma unroll
        for (int j = 0; j < 4; j++) sZ[r][c+j] = y[j];
        for (int t = tid; t < 64*64; t += NTHR) {
            int k = t >> 6, cc2 = t & 63;
            sW[k][cc2] = (k < NcIn) ? Wl[(size_t)k*64 + cc2] : 0.f;
        }
        __syncthreads();
#pragma unroll
        for (int j = 0; j < 4; j++) val[j] = 0.f;
#pragma unroll 8
        for (int k = 0; k < 64; k++) {
            float yv = sZ[r][k];
            val[0] += yv*sW[k][c+0];
            val[1] += yv*sW[k][c+1];
            val[2] += yv*sW[k][c+2];
            val[3] += yv*sW[k][c+3];
        }
#pragma unroll
        for (int j = 0; j < 4; j++) val[j] += bl[c+j];
    } else {
#pragma unroll
        for (int j = 0; j < 4; j++) val[j] = y[j];
    }

#pragma unroll
    for (int j = 0; j < 4; j++) outp[(size_t)row*64 + c + j] = val[j];

    if (csNext) {
        float dN = rsqrtf((float)(pcNext[row] + 1));
        __syncthreads();
#pragma unroll
        for (int j = 0; j < 4; j++) red[r][c+j] = dN*val[j];
        __syncthreads();
        if (tid < 64) {
            float s = 0.f;
#pragma unroll
            for (int rr = 0; rr < 16; rr++) s += red[rr][tid];
            atomicAdd(&csNext[tid], s);
        }
    }
}

// ---------------- the mega kernel ----------------
__global__ void __launch_bounds__(NTHR, 2) mega_kernel(
        const float* __restrict__ x, const float* __restrict__ Aneg, const float* __restrict__ Apos,
        const float* __restrict__ W_l1, const float* __restrict__ b_l1,
        const float* __restrict__ W_l2, const float* __restrict__ b_l2,
        const float* __restrict__ W_l3, const float* __restrict__ b_l3,
        const float* __restrict__ W_g1, const float* __restrict__ b_g1,
        const float* __restrict__ W_g2, const float* __restrict__ b_g2,
        const float* __restrict__ W_g3, const float* __restrict__ b_g3,
        const float* __restrict__ W_g4, const float* __restrict__ b_g4,
        const float* __restrict__ W_g5, const float* __restrict__ b_g5,
        const float* __restrict__ W_g6, const float* __restrict__ b_g6,
        float* __restrict__ out)
{
    __shared__ __align__(16) float smemf[9472];   // 37888 B, covers the largest phase
    int tid = threadIdx.x;
    int nb = gridDim.x;

    // P0: zero
    for (int i = blockIdx.x*NTHR + tid; i < 6*NN;  i += nb*NTHR) g_pc[i] = 0;
    for (int i = blockIdx.x*NTHR + tid; i < 6*256; i += nb*NTHR) g_cs[i] = 0.f;
    for (int i = blockIdx.x*NTHR + tid; i < NN;    i += nb*NTHR) g_cnt[i] = 0;
    gsync();

    // P1: pack (1024 units)
    for (int u = blockIdx.x; u < 1024; u += nb) pack_unit(u, Apos, Aneg, tid);
    gsync();

    // P2: gemm1 (256) + bitstage1 (128)
    for (int u = blockIdx.x; u < 384; u += nb) {
        if (u < 256) gemm1_unit(u, x, W_l1, b_l1, tid, smemf);
        else bitstage_unit(u - 256, (const uint4*)g_lastT[0], (uint4*)g_lastT[1],
                           g_U[0], g_U[1], g_pc + NN, tid, smemf);
    }
    gsync();

    // P3: agg1 (512) + bitstage2 (128)
    for (int u = blockIdx.x; u < 640; u += nb) {
        if (u < 512) agg1_unit(u, W_g1, b_g1, W_l2, b_l2, tid, smemf);
        else bitstage_unit(u - 512, (const uint4*)g_lastT[1], (uint4*)g_lastT[2],
                           g_U[1], g_U[2], g_pc + 2*NN, tid, smemf);
    }
    gsync();

    // P4: agg2 (128) + bitstage3 (128)
    for (int u = blockIdx.x; u < 256; u += nb) {
        if (u < 128) agg64_unit(u, g_xb[0], 62, W_g2, 62, b_g2,
                                g_pc + NN, g_U[1], g_cs + 256, 1.0f, 1,
                                W_l3, b_l3, g_pc + 2*NN, g_cs + 2*256,
                                g_xb[1], tid, smemf);
        else bitstage_unit(u - 128, (const uint4*)g_lastT[2], (uint4*)g_lastT[3],
                           g_U[2], g_U[3], g_pc + 3*NN, tid, smemf);
    }
    gsync();

    // P5: agg3 (128) + bitstage4 (128)
    for (int u = blockIdx.x; u < 256; u += nb) {
        if (u < 128) agg64_unit(u, g_xb[1], 64, W_g3, 64, b_g3,
                                g_pc + 2*NN, g_U[2], g_cs + 2*256, 0.5f, 1,
                                nullptr, nullptr, g_pc + 3*NN, g_cs + 3*256,
                                g_xb[2], tid, smemf);
        else bitstage_unit(u - 128, (const uint4*)g_lastT[3], (uint4*)g_lastT[4],
                           g_U[3], g_U[4], g_pc + 4*NN, tid, smemf);
    }
    gsync();

    // P6: agg4 (128) + bitstage5 (128)
    for (int u = blockIdx.x; u < 256; u += nb) {
        if (u < 128) agg64_unit(u, g_xb[2], 64, W_g4, 64, b_g4,
                                g_pc + 3*NN, g_U[3], g_cs + 3*256, 0.5f, 1,
                                nullptr, nullptr, g_pc + 4*NN, g_cs + 4*256,
                                g_xb[3], tid, smemf);
        else bitstage_unit(u - 128, (const uint4*)g_lastT[4], (uint4*)g_lastT[5],
                           g_U[4], g_U[5], g_pc + 5*NN, tid, smemf);
    }
    gsync();

    // P7: agg5 (128)
    for (int u = blockIdx.x; u < 128; u += nb)
        agg64_unit(u, g_xb[3], 64, W_g5, 64, b_g5,
                   g_pc + 4*NN, g_U[4], g_cs + 4*256, 0.25f, 1,
                   nullptr, nullptr, g_pc + 5*NN, g_cs + 5*256,
                   g_xb[4], tid, smemf);
    gsync();

    // P8: agg6 (128, no relu) -> out
    for (int u = blockIdx.x; u < 128; u += nb)
        agg64_unit(u, g_xb[4], 64, W_g6, 64, b_g6,
                   g_pc + 5*NN, g_U[5], g_cs + 5*256, 0.25f, 0,
                   nullptr, nullptr, nullptr, nullptr,
                   out, tid, smemf);
}

// ---------------- host ----------------
extern "C" void kernel_launch(void* const* d_in, const int* in_sizes, int n_in,
                              void* d_out, int out_size)
{
    const float* x    = (const float*)d_in[0];
    const float* Aneg = (const float*)d_in[1];
    const float* Apos = (const float*)d_in[2];
    const float* W_l1 = (const float*)d_in[3];  const float* b_l1 = (const float*)d_in[4];
    const float* W_l2 = (const float*)d_in[5];  const float* b_l2 = (const float*)d_in[6];
    const float* W_l3 = (const float*)d_in[7];  const float* b_l3 = (const float*)d_in[8];
    const float* W_g1 = (const float*)d_in[9];  const float* b_g1 = (const float*)d_in[10];
    const float* W_g2 = (const float*)d_in[11]; const float* b_g2 = (const float*)d_in[12];
    const float* W_g3 = (const float*)d_in[13]; const float* b_g3 = (const float*)d_in[14];
    const float* W_g4 = (const float*)d_in[15]; const float* b_g4 = (const float*)d_in[16];
    const float* W_g5 = (const float*)d_in[17]; const float* b_g5 = (const float*)d_in[18];
    const float* W_g6 = (const float*)d_in[19]; const float* b_g6 = (const float*)d_in[20];
    float* out = (float*)d_out;

    mega_kernel<<<NBLK, NTHR>>>(x, Aneg, Apos,
                                W_l1, b_l1, W_l2, b_l2, W_l3, b_l3,
                                W_g1, b_g1, W_g2, b_g2, W_g3, b_g3,
                                W_g4, b_g4, W_g5, b_g5, W_g6, b_g6,
                                out);
}

// round 8
// speedup vs baseline: 2.8692x; 2.2113x over previous
#include <cuda_runtime.h>
#include <stdint.h>

#define NN 2048
#define NW 64    // 2048 bits = 64 u32 words
#define CAP 128  // CSC capacity per column of A_pos
#define NBLK 296
#define NTHR 256

// ---------------- device scratch ----------------
__device__ __align__(16) uint32_t g_apT[NN*NW];
__device__ unsigned short g_idx[NN*CAP];
__device__ int      g_cnt[NN];
__device__ __align__(16) uint32_t g_lastT[6][NN*NW];
__device__ __align__(16) uint32_t g_U[6][NN*NW];     // union bits per stage
__device__ int      g_pc[6*NN];
__device__ float    g_cs[6*256];
__device__ unsigned short g_list[6][NN*1024];        // per-row index lists (set or complement)
__device__ int      g_llen[6][NN];                   // len | (comp<<16)
__device__ __align__(16) float g_h1[NN*256];
__device__ __align__(16) float g_t1[NN*256];         // dinv0 .* h1
__device__ __align__(16) float g_xb[5][NN*64];       // h2, h3, x3, x4, x5
__device__ __align__(16) float g_tb[5][NN*64];       // t2..t6
__device__ int          g_barCount = 0;
__device__ volatile int g_barGen   = 0;

// ---------------- software grid barrier ----------------
__device__ __forceinline__ void gsync()
{
    __threadfence();
    __syncthreads();
    if (threadIdx.x == 0) {
        int gen = g_barGen;
        if (atomicAdd(&g_barCount, 1) == (int)gridDim.x - 1) {
            g_barCount = 0;
            __threadfence();
            g_barGen = gen + 1;
        } else {
            while (g_barGen == gen) { __nanosleep(32); }
        }
    }
    __syncthreads();
}

// ---------------- pack: [0,512) A_pos -> apT+CSC ; [512,1024) A_neg -> U0,lastT0,pc0 ----------------
__device__ void pack_unit(int u, const float* __restrict__ Apos, const float* __restrict__ Aneg, int tid)
{
    int lane = tid & 31;
    if (u < 512) {
        int gwarp = u*8 + (tid >> 5);
        int ti = gwarp >> 6, tj = gwarp & 63;
        uint32_t tbits = 0;
#pragma unroll
        for (int r = 0; r < 32; r++) {
            float v = Apos[(size_t)(ti*32 + r)*NN + tj*32 + lane];
            tbits |= (v > 0.f ? 1u : 0u) << r;
        }
        int j = tj*32 + lane;
        g_apT[j*NW + ti] = tbits;
        uint32_t m = tbits;
        while (m) {
            int r = __ffs(m) - 1; m &= (m-1);
            int pos = atomicAdd(&g_cnt[j], 1);
            if (pos < CAP) g_idx[j*CAP + pos] = (unsigned short)(ti*32 + r);
        }
    } else {
        int gwarp = (u - 512)*8 + (tid >> 5);
        int ti = gwarp >> 6, tj = gwarp & 63;
        uint32_t tbits = 0, rw = 0;
#pragma unroll
        for (int r = 0; r < 32; r++) {
            float v = Aneg[(size_t)(ti*32 + r)*NN + tj*32 + lane];
            uint32_t b = (v > 0.f) ? 1u : 0u;
            tbits |= b << r;
            uint32_t m = __ballot_sync(0xffffffffu, b);
            if (lane == r) rw = m;
        }
        g_U[0][(ti*32 + lane)*NW + tj] = rw;
        atomicAdd(&g_pc[ti*32 + lane], __popc(rw));
        g_lastT[0][(tj*32 + lane)*NW + ti] = tbits;
    }
}

// ---------------- bit stage: CSC expand + transpose + OR + pc ----------------
__device__ void bitstage_unit(int v, const uint4* __restrict__ lastOld4, uint4* __restrict__ lastNew4,
                              const uint32_t* __restrict__ uPrev, uint32_t* __restrict__ uCur,
                              int* __restrict__ pcCur, int tid, float* smemf)
{
    uint32_t (*sN)[33] = (uint32_t(*)[33])smemf;
    __syncthreads();
    int jt = v & 63, wt = v >> 6;
    int jl = tid >> 3, w4l = tid & 7;
    int j = jt*32 + jl;
    int w4 = wt*8 + w4l;

    int c = g_cnt[j]; if (c > CAP) c = CAP;
    const unsigned short* lst = g_idx + j*CAP;
    uint4 acc = make_uint4(0u,0u,0u,0u);
    int t = 0;
    for (; t + 4 <= c; t += 4) {
        int k0 = lst[t], k1 = lst[t+1], k2 = lst[t+2], k3 = lst[t+3];
        uint4 v0 = lastOld4[k0*16 + w4];
        uint4 v1 = lastOld4[k1*16 + w4];
        uint4 v2 = lastOld4[k2*16 + w4];
        uint4 v3 = lastOld4[k3*16 + w4];
        acc.x |= v0.x | v1.x | v2.x | v3.x;
        acc.y |= v0.y | v1.y | v2.y | v3.y;
        acc.z |= v0.z | v1.z | v2.z | v3.z;
        acc.w |= v0.w | v1.w | v2.w | v3.w;
    }
    for (; t < c; t++) {
        uint4 vv = lastOld4[lst[t]*16 + w4];
        acc.x |= vv.x; acc.y |= vv.y; acc.z |= vv.z; acc.w |= vv.w;
    }
    lastNew4[j*16 + w4] = acc;
    sN[jl][w4l*4 + 0] = acc.x;
    sN[jl][w4l*4 + 1] = acc.y;
    sN[jl][w4l*4 + 2] = acc.z;
    sN[jl][w4l*4 + 3] = acc.w;
    __syncthreads();

    int warp = tid >> 5, lane = tid & 31;
    for (int wl = warp; wl < 32; wl += 8) {
        uint32_t v2 = sN[lane][wl];
        uint32_t ow = 0;
#pragma unroll
        for (int ib = 0; ib < 32; ib++) {
            uint32_t mm = __ballot_sync(0xffffffffu, (v2 >> ib) & 1u);
            if (lane == ib) ow = mm;
        }
        int i = (wt*32 + wl)*32 + lane;
        uint32_t merged = uPrev[i*NW + jt] | ow;
        uCur[i*NW + jt] = merged;
        atomicAdd(&pcCur[i], __popc(merged));
    }
}

// ---------------- list build: per-row set-bit (or complement) index list ----------------
// unit u in [0,32): 64 rows; 8 warps x 8 rows
__device__ void list_unit(int u, const uint32_t* __restrict__ U, const int* __restrict__ pcS,
                          unsigned short* __restrict__ list, int* __restrict__ llen, int tid)
{
    int warp = tid >> 5, lane = tid & 31;
    for (int rr = 0; rr < 8; rr++) {
        int row = u*64 + warp*8 + rr;
        int pcv = pcS[row];
        bool comp = pcv > 1024;
        uint32_t m0 = U[row*NW + 2*lane];
        uint32_t m1 = U[row*NW + 2*lane + 1];
        if (comp) { m0 = ~m0; m1 = ~m1; }
        int cnt = __popc(m0) + __popc(m1);
        int incl = cnt;
#pragma unroll
        for (int off = 1; off < 32; off <<= 1) {
            int n = __shfl_up_sync(0xffffffffu, incl, off);
            if (lane >= off) incl += n;
        }
        int base = incl - cnt;
        unsigned short* dst = list + (size_t)row*1024 + base;
        int kb = lane*64;
        while (m0) { int b = __ffs(m0)-1; m0 &= (m0-1); *dst++ = (unsigned short)(kb + b); }
        kb += 32;
        while (m1) { int b = __ffs(m1)-1; m1 &= (m1-1); *dst++ = (unsigned short)(kb + b); }
        int total = __shfl_sync(0xffffffffu, incl, 31);
        if (lane == 31) llen[row] = total | (comp ? (1 << 16) : 0);
    }
}

// ---------------- gemm1: h1 = x @ W_l1 + b_l1 (no epilogue extras) ----------------
__device__ void gemm1_unit(int u, const float* __restrict__ A, const float* __restrict__ W,
                           const float* __restrict__ bias, int tid, float* smemf)
{
    float (*As)[34] = (float(*)[34])smemf;            // 544
    float (*Ws)[64] = (float(*)[64])(smemf + 544);    // 1024
    __syncthreads();
    int tx = tid & 15, ty = tid >> 4;
    int rowBase = (u >> 2)*32, colBase = (u & 3)*64;
    float acc[2][4] = {};
    int mA  = tid >> 3, kk2 = (tid & 7)*2;
    int kkW = tid >> 4, cW  = (tid & 15)*4;

    for (int k0 = 0; k0 < 512; k0 += 16) {
        float2 a2 = *(const float2*)(A + (size_t)(rowBase + mA)*512 + k0 + kk2);
        As[kk2][mA]   = a2.x;
        As[kk2+1][mA] = a2.y;
        *(float4*)&Ws[kkW][cW] = *(const float4*)(W + (size_t)(k0 + kkW)*256 + colBase + cW);
        __syncthreads();
#pragma unroll
        for (int kk = 0; kk < 16; kk++) {
            float2 av = *(const float2*)&As[kk][ty*2];
            float4 bv = *(const float4*)&Ws[kk][tx*4];
            acc[0][0] += av.x*bv.x; acc[0][1] += av.x*bv.y;
            acc[0][2] += av.x*bv.z; acc[0][3] += av.x*bv.w;
            acc[1][0] += av.y*bv.x; acc[1][1] += av.y*bv.y;
            acc[1][2] += av.y*bv.z; acc[1][3] += av.y*bv.w;
        }
        __syncthreads();
    }
#pragma unroll
    for (int a = 0; a < 2; a++) {
        int row = rowBase + ty*2 + a;
#pragma unroll
        for (int b = 0; b < 4; b++) {
            int col = colBase + tx*4 + b;
            g_h1[(size_t)row*256 + col] = acc[a][b] + bias[col];
        }
    }
}

// ---------------- t1 = dinv0 .* h1 ; cs0 colsum.  unit u in [0,64): 32 rows ----------------
__device__ void tcs1_unit(int u, int tid, float* smemf)
{
    float (*red)[256] = (float(*)[256])smemf;   // 4*256
    __syncthreads();
    int col4 = (tid & 63)*4;
    int rgrp = tid >> 6;
    int row0 = u*32;
    float s0=0.f, s1=0.f, s2=0.f, s3=0.f;
#pragma unroll
    for (int p = 0; p < 8; p++) {
        int row = row0 + rgrp*8 + p;
        float di = rsqrtf((float)(g_pc[row] + 1));
        float4 hv = *(const float4*)(g_h1 + (size_t)row*256 + col4);
        float4 tv = make_float4(di*hv.x, di*hv.y, di*hv.z, di*hv.w);
        *(float4*)(g_t1 + (size_t)row*256 + col4) = tv;
        s0 += tv.x; s1 += tv.y; s2 += tv.z; s3 += tv.w;
    }
    red[rgrp][col4+0] = s0; red[rgrp][col4+1] = s1;
    red[rgrp][col4+2] = s2; red[rgrp][col4+3] = s3;
    __syncthreads();
    atomicAdd(&g_cs[tid], red[0][tid]+red[1][tid]+red[2][tid]+red[3][tid]);
}

// ---------------- agg1: unit u in [0,256): 8 rows. list-based agg + z@Wg1 + relu residual + x1@W_l2 ----------------
__device__ void agg1_unit(int u, const float* __restrict__ Wg, const float* __restrict__ bg,
                          const float* __restrict__ Wl, const float* __restrict__ bl,
                          int tid, float* smemf)
{
    float (*sZ)[256] = (float(*)[256])smemf;            // 2048
    float (*sX)[256] = (float(*)[256])(smemf + 2048);   // 2048
    float (*red)[64] = (float(*)[64])(smemf + 4096);    // 512
    __syncthreads();
    int row0 = u*8;

    // phase A: z = di*(S + t1_row), S from list0 over t1
    {
        int grp = tid >> 5, lane = tid & 31;
        int f = lane*8;
        int row = row0 + grp;
        int lv = g_llen[0][row];
        int len = lv & 0xFFFF;
        bool comp = (lv >> 16) != 0;
        const unsigned short* L = g_list[0] + (size_t)row*1024;
        float4 a0 = make_float4(0,0,0,0), a1 = make_float4(0,0,0,0);
        int t = 0;
        for (; t + 2 <= len; t += 2) {
            int k0 = L[t], k1 = L[t+1];
            float4 v00 = *(const float4*)(g_t1 + (size_t)k0*256 + f);
            float4 v01 = *(const float4*)(g_t1 + (size_t)k0*256 + f + 4);
            float4 v10 = *(const float4*)(g_t1 + (size_t)k1*256 + f);
            float4 v11 = *(const float4*)(g_t1 + (size_t)k1*256 + f + 4);
            a0.x += v00.x + v10.x; a0.y += v00.y + v10.y;
            a0.z += v00.z + v10.z; a0.w += v00.w + v10.w;
            a1.x += v01.x + v11.x; a1.y += v01.y + v11.y;
            a1.z += v01.z + v11.z; a1.w += v01.w + v11.w;
        }
        for (; t < len; t++) {
            int k0 = L[t];
            float4 v00 = *(const float4*)(g_t1 + (size_t)k0*256 + f);
            float4 v01 = *(const float4*)(g_t1 + (size_t)k0*256 + f + 4);
            a0.x += v00.x; a0.y += v00.y; a0.z += v00.z; a0.w += v00.w;
            a1.x += v01.x; a1.y += v01.y; a1.z += v01.z; a1.w += v01.w;
        }
        if (comp) {
            float4 c0 = *(const float4*)(g_cs + f);
            float4 c1 = *(const float4*)(g_cs + f + 4);
            a0.x = c0.x - a0.x; a0.y = c0.y - a0.y; a0.z = c0.z - a0.z; a0.w = c0.w - a0.w;
            a1.x = c1.x - a1.x; a1.y = c1.y - a1.y; a1.z = c1.z - a1.z; a1.w = c1.w - a1.w;
        }
        float di = rsqrtf((float)(g_pc[row] + 1));
        float4 t0 = *(const float4*)(g_t1 + (size_t)row*256 + f);
        float4 t1v = *(const float4*)(g_t1 + (size_t)row*256 + f + 4);
        sZ[grp][f+0] = di*(a0.x + t0.x); sZ[grp][f+1] = di*(a0.y + t0.y);
        sZ[grp][f+2] = di*(a0.z + t0.z); sZ[grp][f+3] = di*(a0.w + t0.w);
        sZ[grp][f+4] = di*(a1.x + t1v.x); sZ[grp][f+5] = di*(a1.y + t1v.y);
        sZ[grp][f+6] = di*(a1.z + t1v.z); sZ[grp][f+7] = di*(a1.w + t1v.w);
    }
    __syncthreads();

    // phase B: x1 = h1 + relu(z @ Wg + bg); col = tid
    {
        int col = tid;
        float a8[8] = {0,0,0,0,0,0,0,0};
        for (int k = 0; k < 256; k += 4) {
            float w0 = Wg[(size_t)(k+0)*256 + col];
            float w1 = Wg[(size_t)(k+1)*256 + col];
            float w2 = Wg[(size_t)(k+2)*256 + col];
            float w3 = Wg[(size_t)(k+3)*256 + col];
#pragma unroll
            for (int r = 0; r < 8; r++) {
                float4 zq = *(const float4*)&sZ[r][k];
                a8[r] += zq.x*w0 + zq.y*w1 + zq.z*w2 + zq.w*w3;
            }
        }
        float bv = bg[col];
#pragma unroll
        for (int r = 0; r < 8; r++)
            sX[r][col] = g_h1[(size_t)(row0 + r)*256 + col] + fmaxf(a8[r] + bv, 0.f);
    }
    __syncthreads();

    // phase C: h2 = x1 @ W_l2 + b_l2 (62 cols, pad 64); t2 = dinv1*h2; cs1 atomics
    {
        int col = tid & 63;
        int rg = tid >> 6;
        float v0 = 0.f, v1 = 0.f;
        if (col < 62) {
            for (int k = 0; k < 256; k += 4) {
                float w0 = Wl[(size_t)(k+0)*62 + col];
                float w1 = Wl[(size_t)(k+1)*62 + col];
                float w2 = Wl[(size_t)(k+2)*62 + col];
                float w3 = Wl[(size_t)(k+3)*62 + col];
                float4 xa = *(const float4*)&sX[rg*2][k];
                float4 xb = *(const float4*)&sX[rg*2+1][k];
                v0 += xa.x*w0 + xa.y*w1 + xa.z*w2 + xa.w*w3;
                v1 += xb.x*w0 + xb.y*w1 + xb.z*w2 + xb.w*w3;
            }
            float bv = bl[col];
            v0 += bv; v1 += bv;
        }
        int rA = row0 + rg*2, rB = rA + 1;
        float dA = rsqrtf((float)(g_pc[NN + rA] + 1));
        float dB = rsqrtf((float)(g_pc[NN + rB] + 1));
        g_xb[0][(size_t)rA*64 + col] = v0;
        g_xb[0][(size_t)rB*64 + col] = v1;
        float tA = dA*v0, tB = dB*v1;
        g_tb[0][(size_t)rA*64 + col] = tA;
        g_tb[0][(size_t)rB*64 + col] = tB;
        red[rg*2][col] = tA;
        red[rg*2+1][col] = tB;
    }
    __syncthreads();
    if (tid < 64) {
        float s = 0.f;
#pragma unroll
        for (int r = 0; r < 8; r++) s += red[r][tid];
        atomicAdd(&g_cs[256 + tid], s);
    }
}

// ---------------- agg64: unit u in [0,128): 16 rows. list-based ----------------
__device__ void agg64_unit(int u,
        const float* __restrict__ h, const float* __restrict__ tArr, int NcIn,
        const float* __restrict__ Wg, int ldwg, const float* __restrict__ bg,
        const int* __restrict__ pcS,
        const unsigned short* __restrict__ lst, const int* __restrict__ llen,
        const float* __restrict__ cs,
        float wscale, int doRelu,
        const float* __restrict__ Wl, const float* __restrict__ bl,
        const int* __restrict__ pcNext, float* __restrict__ tNext, float* __restrict__ csNext,
        float* __restrict__ outp, int tid, float* smemf)
{
    float (*sW)[64] = (float(*)[64])smemf;            // 4096
    float (*sZ)[64] = (float(*)[64])(smemf + 4096);   // 1024
    float (*red)[64] = (float(*)[64])(smemf + 5120);  // 1024
    __syncthreads();
    int row0 = u*16;

    for (int t = tid; t < 64*64; t += NTHR) {
        int k = t >> 6, c = t & 63;
        sW[k][c] = (k < NcIn && c < NcIn) ? Wg[(size_t)k*ldwg + c] : 0.f;
    }

    // phase A
    {
        int grp = tid >> 4, lane = tid & 15;
        int f = lane*4;
        int row = row0 + grp;
        int lv = llen[row];
        int len = lv & 0xFFFF;
        bool comp = (lv >> 16) != 0;
        const unsigned short* L = lst + (size_t)row*1024;
        float4 acc = make_float4(0,0,0,0);
        int t = 0;
        for (; t + 4 <= len; t += 4) {
            ushort4 k4 = *(const ushort4*)(L + t);
            float4 a = *(const float4*)(tArr + (size_t)k4.x*64 + f);
            float4 b = *(const float4*)(tArr + (size_t)k4.y*64 + f);
            float4 c2 = *(const float4*)(tArr + (size_t)k4.z*64 + f);
            float4 d = *(const float4*)(tArr + (size_t)k4.w*64 + f);
            acc.x += (a.x + b.x) + (c2.x + d.x);
            acc.y += (a.y + b.y) + (c2.y + d.y);
            acc.z += (a.z + b.z) + (c2.z + d.z);
            acc.w += (a.w + b.w) + (c2.w + d.w);
        }
        for (; t < len; t++) {
            float4 a = *(const float4*)(tArr + (size_t)L[t]*64 + f);
            acc.x += a.x; acc.y += a.y; acc.z += a.z; acc.w += a.w;
        }
        if (comp) {
            float4 c4 = *(const float4*)(cs + f);
            acc.x = c4.x - acc.x; acc.y = c4.y - acc.y;
            acc.z = c4.z - acc.z; acc.w = c4.w - acc.w;
        }
        float di = rsqrtf((float)(pcS[row] + 1));
        float4 tr = *(const float4*)(tArr + (size_t)row*64 + f);
        sZ[grp][f+0] = di*(acc.x + tr.x);
        sZ[grp][f+1] = di*(acc.y + tr.y);
        sZ[grp][f+2] = di*(acc.z + tr.z);
        sZ[grp][f+3] = di*(acc.w + tr.w);
    }
    __syncthreads();

    // phase B: y = h + wscale*act(z@Wg + bg)
    int r = tid >> 4;
    int c = (tid & 15)*4;
    int row = row0 + r;
    float y[4] = {0.f, 0.f, 0.f, 0.f};
#pragma unroll 8
    for (int k = 0; k < 64; k++) {
        float zv = sZ[r][k];
        y[0] += zv*sW[k][c+0];
        y[1] += zv*sW[k][c+1];
        y[2] += zv*sW[k][c+2];
        y[3] += zv*sW[k][c+3];
    }
#pragma unroll
    for (int j = 0; j < 4; j++) {
        int cc = c + j;
        float b = (cc < NcIn) ? bg[cc] : 0.f;
        float v = y[j] + b;
        if (doRelu) v = fmaxf(v, 0.f);
        y[j] = h[(size_t)row*64 + cc] + wscale*v;
    }

    float val[4];
    if (Wl) {
        __syncthreads();
#pragma unroll
        for (int j = 0; j < 4; j++) sZ[r][c+j] = y[j];
        for (int t = tid; t < 64*64; t += NTHR) {
            int k = t >> 6, cc2 = t & 63;
            sW[k][cc2] = (k < NcIn) ? Wl[(size_t)k*64 + cc2] : 0.f;
        }
        __syncthreads();
#pragma unroll
        for (int j = 0; j < 4; j++) val[j] = 0.f;
#pragma unroll 8
        for (int k = 0; k < 64; k++) {
            float yv = sZ[r][k];
            val[0] += yv*sW[k][c+0];
            val[1] += yv*sW[k][c+1];
            val[2] += yv*sW[k][c+2];
            val[3] += yv*sW[k][c+3];
        }
#pragma unroll
        for (int j = 0; j < 4; j++) val[j] += bl[c+j];
    } else {
#pragma unroll
        for (int j = 0; j < 4; j++) val[j] = y[j];
    }

#pragma unroll
    for (int j = 0; j < 4; j++) outp[(size_t)row*64 + c + j] = val[j];

    if (csNext) {
        float dN = rsqrtf((float)(pcNext[row] + 1));
        __syncthreads();
#pragma unroll
        for (int j = 0; j < 4; j++) {
            float tv = dN*val[j];
            tNext[(size_t)row*64 + c + j] = tv;
            red[r][c+j] = tv;
        }
        __syncthreads();
        if (tid < 64) {
            float s = 0.f;
#pragma unroll
            for (int rr = 0; rr < 16; rr++) s += red[rr][tid];
            atomicAdd(&csNext[tid], s);
        }
    }
}

// ---------------- the mega kernel ----------------
__global__ void __launch_bounds__(NTHR, 2) mega_kernel(
        const float* __restrict__ x, const float* __restrict__ Aneg, const float* __restrict__ Apos,
        const float* __restrict__ W_l1, const float* __restrict__ b_l1,
        const float* __restrict__ W_l2, const float* __restrict__ b_l2,
        const float* __restrict__ W_l3, const float* __restrict__ b_l3,
        const float* __restrict__ W_g1, const float* __restrict__ b_g1,
        const float* __restrict__ W_g2, const float* __restrict__ b_g2,
        const float* __restrict__ W_g3, const float* __restrict__ b_g3,
        const float* __restrict__ W_g4, const float* __restrict__ b_g4,
        const float* __restrict__ W_g5, const float* __restrict__ b_g5,
        const float* __restrict__ W_g6, const float* __restrict__ b_g6,
        float* __restrict__ out)
{
    __shared__ __align__(16) float smemf[6144];   // 24 KB
    int tid = threadIdx.x;
    int nb = gridDim.x;

    // P0: zero
    for (int i = blockIdx.x*NTHR + tid; i < 6*NN;  i += nb*NTHR) g_pc[i] = 0;
    for (int i = blockIdx.x*NTHR + tid; i < 6*256; i += nb*NTHR) g_cs[i] = 0.f;
    for (int i = blockIdx.x*NTHR + tid; i < NN;    i += nb*NTHR) g_cnt[i] = 0;
    gsync();

    // P1: pack (1024) + gemm1 (256)
    for (int u = blockIdx.x; u < 1280; u += nb) {
        if (u < 1024) pack_unit(u, Apos, Aneg, tid);
        else gemm1_unit(u - 1024, x, W_l1, b_l1, tid, smemf);
    }
    gsync();

    // P2: tcs1 (64) + bitstage1 (128) + list0 (32)
    for (int u = blockIdx.x; u < 224; u += nb) {
        if (u < 64) tcs1_unit(u, tid, smemf);
        else if (u < 192) bitstage_unit(u - 64, (const uint4*)g_lastT[0], (uint4*)g_lastT[1],
                                        g_U[0], g_U[1], g_pc + NN, tid, smemf);
        else list_unit(u - 192, g_U[0], g_pc, g_list[0], g_llen[0], tid);
    }
    gsync();

    // P3: agg1 (256) + bitstage2 (128) + list1 (32)
    for (int u = blockIdx.x; u < 416; u += nb) {
        if (u < 256) agg1_unit(u, W_g1, b_g1, W_l2, b_l2, tid, smemf);
        else if (u < 384) bitstage_unit(u - 256, (const uint4*)g_lastT[1], (uint4*)g_lastT[2],
                                        g_U[1], g_U[2], g_pc + 2*NN, tid, smemf);
        else list_unit(u - 384, g_U[1], g_pc + NN, g_list[1], g_llen[1], tid);
    }
    gsync();

    // P4: agg2 (128) + bitstage3 (128) + list2 (32)
    for (int u = blockIdx.x; u < 288; u += nb) {
        if (u < 128) agg64_unit(u, g_xb[0], g_tb[0], 62, W_g2, 62, b_g2,
                                g_pc + NN, g_list[1], g_llen[1], g_cs + 256,
                                1.0f, 1, W_l3, b_l3,
                                g_pc + 2*NN, g_tb[1], g_cs + 2*256,
                                g_xb[1], tid, smemf);
        else if (u < 256) bitstage_unit(u - 128, (const uint4*)g_lastT[2], (uint4*)g_lastT[3],
                                        g_U[2], g_U[3], g_pc + 3*NN, tid, smemf);
        else list_unit(u - 256, g_U[2], g_pc + 2*NN, g_list[2], g_llen[2], tid);
    }
    gsync();

    // P5: agg3 (128) + bitstage4 (128) + list3 (32)
    for (int u = blockIdx.x; u < 288; u += nb) {
        if (u < 128) agg64_unit(u, g_xb[1], g_tb[1], 64, W_g3, 64, b_g3,
                                g_pc + 2*NN, g_list[2], g_llen[2], g_cs + 2*256,
                                0.5f, 1, nullptr, nullptr,
                                g_pc + 3*NN, g_tb[2], g_cs + 3*256,
                                g_xb[2], tid, smemf);
        else if (u < 256) bitstage_unit(u - 128, (const uint4*)g_lastT[3], (uint4*)g_lastT[4],
                                        g_U[3], g_U[4], g_pc + 4*NN, tid, smemf);
        else list_unit(u - 256, g_U[3], g_pc + 3*NN, g_list[3], g_llen[3], tid);
    }
    gsync();

    // P6: agg4 (128) + bitstage5 (128) + list4 (32)
    for (int u = blockIdx.x; u < 288; u += nb) {
        if (u < 128) agg64_unit(u, g_xb[2], g_tb[2], 64, W_g4, 64, b_g4,
                                g_pc + 3*NN, g_list[3], g_llen[3], g_cs + 3*256,
                                0.5f, 1, nullptr, nullptr,
                                g_pc + 4*NN, g_tb[3], g_cs + 4*256,
                                g_xb[3], tid, smemf);
        else if (u < 256) bitstage_unit(u - 128, (const uint4*)g_lastT[4], (uint4*)g_lastT[5],
                                        g_U[4], g_U[5], g_pc + 5*NN, tid, smemf);
        else list_unit(u - 256, g_U[4], g_pc + 4*NN, g_list[4], g_llen[4], tid);
    }
    gsync();

    // P7: agg5 (128) + list5 (32)
    for (int u = blockIdx.x; u < 160; u += nb) {
        if (u < 128) agg64_unit(u, g_xb[3], g_tb[3], 64, W_g5, 64, b_g5,
                                g_pc + 4*NN, g_list[4], g_llen[4], g_cs + 4*256,
                                0.25f, 1, nullptr, nullptr,
                                g_pc + 5*NN, g_tb[4], g_cs + 5*256,
                                g_xb[4], tid, smemf);
        else list_unit(u - 128, g_U[5], g_pc + 5*NN, g_list[5], g_llen[5], tid);
    }
    gsync();

    // P8: agg6 (128, no relu) -> out
    for (int u = blockIdx.x; u < 128; u += nb)
        agg64_unit(u, g_xb[4], g_tb[4], 64, W_g6, 64, b_g6,
                   g_pc + 5*NN, g_list[5], g_llen[5], g_cs + 5*256,
                   0.25f, 0, nullptr, nullptr,
                   nullptr, nullptr, nullptr,
                   out, tid, smemf);
}

// ---------------- host ----------------
extern "C" void kernel_launch(void* const* d_in, const int* in_sizes, int n_in,
                              void* d_out, int out_size)
{
    const float* x    = (const float*)d_in[0];
    const float* Aneg = (const float*)d_in[1];
    const float* Apos = (const float*)d_in[2];
    const float* W_l1 = (const float*)d_in[3];  const float* b_l1 = (const float*)d_in[4];
    const float* W_l2 = (const float*)d_in[5];  const float* b_l2 = (const float*)d_in[6];
    const float* W_l3 = (const float*)d_in[7];  const float* b_l3 = (const float*)d_in[8];
    const float* W_g1 = (const float*)d_in[9];  const float* b_g1 = (const float*)d_in[10];
    const float* W_g2 = (const float*)d_in[11]; const float* b_g2 = (const float*)d_in[12];
    const float* W_g3 = (const float*)d_in[13]; const float* b_g3 = (const float*)d_in[14];
    const float* W_g4 = (const float*)d_in[15]; const float* b_g4 = (const float*)d_in[16];
    const float* W_g5 = (const float*)d_in[17]; const float* b_g5 = (const float*)d_in[18];
    const float* W_g6 = (const float*)d_in[19]; const float* b_g6 = (const float*)d_in[20];
    float* out = (float*)d_out;

    mega_kernel<<<NBLK, NTHR>>>(x, Aneg, Apos,
                                W_l1, b_l1, W_l2, b_l2, W_l3, b_l3,
                                W_g1, b_g1, W_g2, b_g2, W_g3, b_g3,
                                W_g4, b_g4, W_g5, b_g5, W_g6, b_g6,
                                out);
}